// round 13
// baseline (speedup 1.0000x reference)
#include <cuda_runtime.h>
#include <math.h>
#include <stdint.h>

#define HD 256
#define DD 64

__device__ float g_W1T[2 * DD * HD];   // [pass][(j*64 + m)]
__device__ float g_W2T[2 * HD * HD];   // [pass][(k*256 + j)]

__global__ void prep_kernel(const float* __restrict__ W1m, const float* __restrict__ W2m,
                            const float* __restrict__ W1q, const float* __restrict__ W2q)
{
    int t = blockIdx.x * blockDim.x + threadIdx.x;
    if (t < DD * HD) {
        int j = t >> 6, m = t & 63;
        g_W1T[t]           = W1m[m * HD + j];
        g_W1T[DD * HD + t] = W1q[m * HD + j];
    }
    if (t < HD * HD) {
        int k = t >> 8, j = t & 255;
        g_W2T[t]           = W2m[j * HD + k];
        g_W2T[HD * HD + t] = W2q[j * HD + k];
    }
}

__device__ __forceinline__ uint32_t to_tf32(float x) {
    uint32_t r;
    asm("cvt.rna.tf32.f32 %0, %1;" : "=r"(r) : "f"(x));
    return r;
}

#define MMA_TF32(acc, a0, a1, a2, a3, b0, b1)                                   \
    asm volatile(                                                               \
        "mma.sync.aligned.m16n8k8.row.col.f32.tf32.tf32.f32 "                   \
        "{%0,%1,%2,%3}, {%4,%5,%6,%7}, {%8,%9}, {%0,%1,%2,%3};\n"               \
        : "+f"(acc[0]), "+f"(acc[1]), "+f"(acc[2]), "+f"(acc[3])                \
        : "r"(a0), "r"(a1), "r"(a2), "r"(a3), "r"(b0), "r"(b1))

// Shared memory (floats), NS=2 samples per CTA, n-chunked M (occupancy 3):
//   Mt2  [2][64][68]   8704  M n-chunk (64 n) per sample (k-major); Sv in solve
//   W2s  [16][72]      1152  tf32 W2 (j x 64-n-chunk) tile
//   Asj2 [16][136]     2176  tf32 scaled A tile (m' = 2x64); H1 W1T tile
//   Hs2  [2][32][65]   4160  H rows 32..63 per sample; col 64 = gsA (rows 0..31)
//   vA/vB/vC/vD/vE 512 each
//   xs 128
// Total 18,880 floats = 75,520 B -> 3 CTAs/SM.
#define SMEM_FLOATS (8704 + 1152 + 2176 + 4160 + 5*512 + 128)
#define SMEM_BYTES  (SMEM_FLOATS * 4)

__global__ __launch_bounds__(256, 3)
void lnn_kernel(const float* __restrict__ x,
                const float* __restrict__ W1m, const float* __restrict__ b1m,
                const float* __restrict__ W2m, const float* __restrict__ b2m,
                const float* __restrict__ W3m,
                const float* __restrict__ W1q, const float* __restrict__ b1q,
                const float* __restrict__ W2q, const float* __restrict__ b2q,
                const float* __restrict__ W3q,
                float* __restrict__ out)
{
    extern __shared__ float sm[];
    float* Mt2  = sm;                // 8704 (pitch 68; sample stride 4352)
    float* W2s  = Mt2 + 8704;        // 1152 (pitch 72)
    float* Asj2 = W2s + 1152;        // 2176 (pitch 136)
    float* Hs2  = Asj2 + 2176;       // 4160 (pitch 65; col 64 = gsA)
    float* vA   = Hs2 + 4160;        // 512
    float* vB   = vA + 512;          // 512
    float* vC   = vB + 512;          // 512
    float* vD   = vC + 512;          // 512
    float* vE   = vD + 512;          // 512
    float* xs   = vE + 512;          // 128

    const int tid = threadIdx.x;
    const int b   = blockIdx.x;      // samples 2b, 2b+1

    for (int q = tid; q < 4160; q += 256) Hs2[q] = 0.0f;
    if (tid < 128) xs[tid] = x[b * 128 + tid];
    __syncthreads();

    const int wid = tid >> 5, lane = tid & 31;
    const int g = lane >> 2, t4 = lane & 3;

    #pragma unroll 1
    for (int pass = 0; pass < 2; pass++) {
        const float* W1  = pass ? W1q : W1m;
        const float* b1  = pass ? b1q : b1m;
        const float* W2  = pass ? W2q : W2m;
        const float* b2  = pass ? b2q : b2m;
        const float* W3  = pass ? W3q : W3m;
        const float* W1T = g_W1T + pass * (DD * HD);
        const float* W2T = g_W2T + pass * (HD * HD);

        // ---- Stage 1: z1 = x W1 + b1 (both samples); h1, a, s ----
        {
            int j = tid;
            float bv = b1[j];
            float p0 = bv, p1 = 0.f, p2 = 0.f, p3 = 0.f;
            float q0 = bv, q1 = 0.f, q2 = 0.f, q3 = 0.f;
            const float4* x0 = (const float4*)xs;
            const float4* x1 = (const float4*)(xs + 64);
            #pragma unroll 4
            for (int i4 = 0; i4 < 16; i4++) {
                int i = i4 * 4;
                float w0 = W1[(i + 0) * HD + j];
                float w1 = W1[(i + 1) * HD + j];
                float w2 = W1[(i + 2) * HD + j];
                float w3 = W1[(i + 3) * HD + j];
                float4 u0 = x0[i4], u1 = x1[i4];
                p0 = fmaf(u0.x, w0, p0); q0 = fmaf(u1.x, w0, q0);
                p1 = fmaf(u0.y, w1, p1); q1 = fmaf(u1.y, w1, q1);
                p2 = fmaf(u0.z, w2, p2); q2 = fmaf(u1.z, w2, q2);
                p3 = fmaf(u0.w, w3, p3); q3 = fmaf(u1.w, w3, q3);
            }
            float z0v = (p0 + p1) + (p2 + p3);
            float z1v = (q0 + q1) + (q2 + q3);
            #pragma unroll
            for (int ns = 0; ns < 2; ns++) {
                float z = ns ? z1v : z0v;
                float h, a, s;
                if (pass == 0) {
                    float sg = 1.0f / (1.0f + __expf(-z));
                    h = fmaxf(z, 0.0f) + log1pf(__expf(-fabsf(z)));
                    a = sg;
                    s = sg * (1.0f - sg);
                } else {
                    float t = tanhf(0.5f * z);
                    float o = 1.0f - t * t;
                    h = z * t;
                    a = fmaf(0.5f * z, o, t);
                    s = o * (1.0f - 0.5f * z * t);
                }
                vA[ns * 256 + j] = h;
                vC[ns * 256 + j] = a;
                vD[ns * 256 + j] = s;
            }
        }
        __syncthreads();

        // ---- Stage 2: z2 = h1 W2 + b2 ; c, e ----
        {
            int k = tid;
            float bv = b2[k];
            float p0 = bv, p1 = 0.f, p2 = 0.f, p3 = 0.f;
            float q0 = bv, q1 = 0.f, q2 = 0.f, q3 = 0.f;
            const float4* h0 = (const float4*)vA;
            const float4* h1v = (const float4*)(vA + 256);
            #pragma unroll 4
            for (int l4 = 0; l4 < 64; l4++) {
                int l = l4 * 4;
                float w0 = W2[(l + 0) * HD + k];
                float w1 = W2[(l + 1) * HD + k];
                float w2 = W2[(l + 2) * HD + k];
                float w3 = W2[(l + 3) * HD + k];
                float4 u0 = h0[l4], u1 = h1v[l4];
                p0 = fmaf(u0.x, w0, p0); q0 = fmaf(u1.x, w0, q0);
                p1 = fmaf(u0.y, w1, p1); q1 = fmaf(u1.y, w1, q1);
                p2 = fmaf(u0.z, w2, p2); q2 = fmaf(u1.z, w2, q2);
                p3 = fmaf(u0.w, w3, p3); q3 = fmaf(u1.w, w3, q3);
            }
            float z0v = (p0 + p1) + (p2 + p3);
            float z1v = (q0 + q1) + (q2 + q3);
            float w3v = W3[k];
            #pragma unroll
            for (int ns = 0; ns < 2; ns++) {
                float z = ns ? z1v : z0v;
                float a, s;
                if (pass == 0) {
                    float sg = 1.0f / (1.0f + __expf(-z));
                    a = sg;
                    s = sg * (1.0f - sg);
                } else {
                    float t = tanhf(0.5f * z);
                    float o = 1.0f - t * t;
                    a = fmaf(0.5f * z, o, t);
                    s = o * (1.0f - 0.5f * z * t);
                }
                vB[ns * 256 + k] = a * w3v;
                vE[ns * 256 + k] = s * w3v;
            }
        }
        __syncthreads();

        // ---- Stage 3: u = W2 c ; dds = s*u, aus = a*u ----
        {
            int j = tid;
            float p0 = 0.f, p1 = 0.f, p2 = 0.f, p3 = 0.f;
            float q0 = 0.f, q1 = 0.f, q2 = 0.f, q3 = 0.f;
            const float4* c0 = (const float4*)vB;
            const float4* c1 = (const float4*)(vB + 256);
            #pragma unroll 4
            for (int k4 = 0; k4 < 64; k4++) {
                int k = k4 * 4;
                float w0 = W2T[(k + 0) * HD + j];
                float w1 = W2T[(k + 1) * HD + j];
                float w2 = W2T[(k + 2) * HD + j];
                float w3 = W2T[(k + 3) * HD + j];
                float4 u0 = c0[k4], u1 = c1[k4];
                p0 = fmaf(u0.x, w0, p0); q0 = fmaf(u1.x, w0, q0);
                p1 = fmaf(u0.y, w1, p1); q1 = fmaf(u1.y, w1, q1);
                p2 = fmaf(u0.z, w2, p2); q2 = fmaf(u1.z, w2, q2);
                p3 = fmaf(u0.w, w3, p3); q3 = fmaf(u1.w, w3, q3);
            }
            float u0v = (p0 + p1) + (p2 + p3);
            float u1v = (q0 + q1) + (q2 + q3);
            float s0 = vD[j], s1 = vD[256 + j];
            float a0 = vC[j], a1 = vC[256 + j];
            vD[j]       = s0 * u0v;  vD[256 + j] = s1 * u1v;
            vA[j]       = a0 * u0v;  vA[256 + j] = a1 * u1v;
        }
        __syncthreads();

        // ---- Stage 4: g = W1 (a*u), 4-way j-split, both samples ----
        {
            int m = tid & 63, part = tid >> 6;
            const float* W1Tp = W1T + part * 64 * 64;
            const float4* a0 = (const float4*)(vA + part * 64);
            const float4* a1 = (const float4*)(vA + 256 + part * 64);
            float p0 = 0.f, p1 = 0.f, p2 = 0.f, p3 = 0.f;
            float q0 = 0.f, q1 = 0.f, q2 = 0.f, q3 = 0.f;
            #pragma unroll 4
            for (int j4 = 0; j4 < 16; j4++) {
                int jj = j4 * 4;
                float w0 = W1Tp[(jj + 0) * 64 + m];
                float w1 = W1Tp[(jj + 1) * 64 + m];
                float w2 = W1Tp[(jj + 2) * 64 + m];
                float w3 = W1Tp[(jj + 3) * 64 + m];
                float4 u0 = a0[j4], u1 = a1[j4];
                p0 = fmaf(w0, u0.x, p0); q0 = fmaf(w0, u1.x, q0);
                p1 = fmaf(w1, u0.y, p1); q1 = fmaf(w1, u1.y, q1);
                p2 = fmaf(w2, u0.z, p2); q2 = fmaf(w2, u1.z, q2);
                p3 = fmaf(w3, u0.w, p3); q3 = fmaf(w3, u1.w, q3);
            }
            float g0 = (p0 + p1) + (p2 + p3);
            float g1 = (q0 + q1) + (q2 + q3);
            vB[part * 64 + m]       = g0;   // ccs dead after stage 3 sync
            vB[256 + part * 64 + m] = g1;
        }
        __syncthreads();
        // Only g[0..31] feeds the solve; Hs2 has 32 rows per sample.
        if (tid < 64) {
            int ns = tid >> 5, mm = tid & 31;
            const float* gp = vB + ns * 256;
            Hs2[ns * 2080 + mm * 65 + 64] += gp[mm] + gp[64 + mm] + gp[128 + mm] + gp[192 + mm];
        }

        // ---- Stage 5+H2 fused per n-chunk of 64 (TENSOR), 4 chunks ----
        // Warp tiling 2m x 4n: warp = (m-pair mp, n-half nh of 32).
        const int mp  = wid & 3;           // m rows mp*32 .. +31 (m' = 2x64)
        const int nh  = wid >> 2;          // n cols nh*32 .. +31 (4 n-tiles)
        const int s5  = wid & 1;           // H-phase sample
        const int nH  = (wid >> 1) * 16;   // H-phase col group
        const float4* W2v  = (const float4*)W2;
        const float4* W1Tv = (const float4*)W1T;

        #pragma unroll 1
        for (int ktile = 0; ktile < 4; ktile++) {
            float acc[2][4][4];
            #pragma unroll
            for (int mi = 0; mi < 2; mi++)
                #pragma unroll
                for (int i = 0; i < 4; i++)
                    #pragma unroll
                    for (int j = 0; j < 4; j++) acc[mi][i][j] = 0.f;

            #pragma unroll 1
            for (int jt = 0; jt < 256; jt += 16) {
                // stage A (both samples, scaled): 2 float4/thread, pitch 136
                #pragma unroll
                for (int r = 0; r < 2; r++) {
                    int f = tid + r * 256;
                    int jl = f >> 5, m4 = f & 31;
                    int smp = m4 >> 4;
                    float4 v = W1Tv[(jt + jl) * 16 + (m4 & 15)];
                    float aw = vC[smp * 256 + jt + jl];
                    float4 o;
                    o.x = __uint_as_float(to_tf32(v.x * aw));
                    o.y = __uint_as_float(to_tf32(v.y * aw));
                    o.z = __uint_as_float(to_tf32(v.z * aw));
                    o.w = __uint_as_float(to_tf32(v.w * aw));
                    *(float4*)(Asj2 + jl * 136 + m4 * 4) = o;
                }
                // stage B (64-n chunk): 1 float4/thread, pitch 72
                {
                    int jl = tid >> 4, n4 = tid & 15;
                    float4 v = W2v[(jt + jl) * 64 + ktile * 16 + n4];
                    float4 o;
                    o.x = __uint_as_float(to_tf32(v.x));
                    o.y = __uint_as_float(to_tf32(v.y));
                    o.z = __uint_as_float(to_tf32(v.z));
                    o.w = __uint_as_float(to_tf32(v.w));
                    *(float4*)(W2s + jl * 72 + n4 * 4) = o;
                }
                __syncthreads();

                #pragma unroll
                for (int s = 0; s < 2; s++) {
                    int jb = s * 8;
                    const float* ar0 = Asj2 + (jb + t4) * 136;
                    const float* ar1 = Asj2 + (jb + t4 + 4) * 136;
                    uint32_t af[2][4];
                    #pragma unroll
                    for (int mi = 0; mi < 2; mi++) {
                        int mb = mp * 32 + mi * 16;
                        af[mi][0] = __float_as_uint(ar0[mb + g]);
                        af[mi][1] = __float_as_uint(ar0[mb + g + 8]);
                        af[mi][2] = __float_as_uint(ar1[mb + g]);
                        af[mi][3] = __float_as_uint(ar1[mb + g + 8]);
                    }
                    const float* br0 = W2s + (jb + t4) * 72;
                    const float* br1 = W2s + (jb + t4 + 4) * 72;
                    #pragma unroll
                    for (int nt = 0; nt < 4; nt++) {
                        int nb = nh * 32 + nt * 8;
                        uint32_t b0 = __float_as_uint(br0[nb + g]);
                        uint32_t b1 = __float_as_uint(br1[nb + g]);
                        MMA_TF32(acc[0][nt], af[0][0], af[0][1], af[0][2], af[0][3], b0, b1);
                        MMA_TF32(acc[1][nt], af[1][0], af[1][1], af[1][2], af[1][3], b0, b1);
                    }
                }
                __syncthreads();
            }

            // epilogue: Mt2[sample][n 0..63][m] (k-major per sample)
            {
                int smp = mp >> 1;
                float* Mbase = Mt2 + smp * 4352;
                #pragma unroll
                for (int mi = 0; mi < 2; mi++) {
                    int mloc = (mp & 1) * 32 + mi * 16 + g;
                    #pragma unroll
                    for (int nt = 0; nt < 4; nt++) {
                        int n0 = nh * 32 + nt * 8 + t4 * 2;
                        Mbase[n0 * 68 + mloc]           = acc[mi][nt][0];
                        Mbase[(n0 + 1) * 68 + mloc]     = acc[mi][nt][1];
                        Mbase[n0 * 68 + mloc + 8]       = acc[mi][nt][2];
                        Mbase[(n0 + 1) * 68 + mloc + 8] = acc[mi][nt][3];
                    }
                }
            }
            __syncthreads();

            // H2 over this 64-k chunk: Hs2[s5] += sum_k e_k M[k][32+i] M[k][j]
            {
                float hacc[2][2][4];
                #pragma unroll
                for (int a = 0; a < 2; a++)
                    #pragma unroll
                    for (int c = 0; c < 2; c++)
                        #pragma unroll
                        for (int d = 0; d < 4; d++) hacc[a][c][d] = 0.f;

                const float* eesN = vE + s5 * 256 + ktile * 64;
                #pragma unroll 2
                for (int kk = 0; kk < 64; kk += 8) {
                    const float* r0 = Mt2 + s5 * 4352 + (kk + t4) * 68;
                    const float* r1 = r0 + 4 * 68;
                    float w0 = eesN[kk + t4];
                    float w1 = eesN[kk + t4 + 4];
                    uint32_t af[2][4];
                    #pragma unroll
                    for (int mi = 0; mi < 2; mi++) {
                        int mH = mi * 16;
                        af[mi][0] = to_tf32(r0[32 + mH + g] * w0);
                        af[mi][1] = to_tf32(r0[32 + mH + g + 8] * w0);
                        af[mi][2] = to_tf32(r1[32 + mH + g] * w1);
                        af[mi][3] = to_tf32(r1[32 + mH + g + 8] * w1);
                    }
                    #pragma unroll
                    for (int nt = 0; nt < 2; nt++) {
                        int nb = nH + nt * 8;
                        uint32_t b0 = to_tf32(r0[nb + g]);
                        uint32_t b1 = to_tf32(r1[nb + g]);
                        MMA_TF32(hacc[0][nt], af[0][0], af[0][1], af[0][2], af[0][3], b0, b1);
                        MMA_TF32(hacc[1][nt], af[1][0], af[1][1], af[1][2], af[1][3], b0, b1);
                    }
                }
                float* HsS = Hs2 + s5 * 2080;
                #pragma unroll
                for (int mi = 0; mi < 2; mi++)
                    #pragma unroll
                    for (int nt = 0; nt < 2; nt++) {
                        int j0 = nH + nt * 8 + t4 * 2;
                        int row = mi * 16 + g;
                        HsS[row * 65 + j0]           += hacc[mi][nt][0];
                        HsS[row * 65 + j0 + 1]       += hacc[mi][nt][1];
                        HsS[(row + 8) * 65 + j0]     += hacc[mi][nt][2];
                        HsS[(row + 8) * 65 + j0 + 1] += hacc[mi][nt][3];
                    }
            }
            __syncthreads();
        }

        // ---- H1 (TENSOR): Hs2[s] += sum_k d_k W1T[k][32+i] W1T[k][j] ----
        {
            float hacc[2][2][4];
            #pragma unroll
            for (int a = 0; a < 2; a++)
                #pragma unroll
                for (int c = 0; c < 2; c++)
                    #pragma unroll
                    for (int d = 0; d < 4; d++) hacc[a][c][d] = 0.f;

            const float* ddsN = vD + s5 * 256;
            #pragma unroll 1
            for (int kt = 0; kt < 256; kt += 16) {
                {
                    int kl = tid >> 4, m4 = tid & 15;
                    *(float4*)(Asj2 + kl * 136 + m4 * 4) = W1Tv[(kt + kl) * 16 + m4];
                }
                __syncthreads();
                #pragma unroll
                for (int s = 0; s < 2; s++) {
                    int kb = s * 8;
                    const float* r0 = Asj2 + (kb + t4) * 136;
                    const float* r1 = Asj2 + (kb + t4 + 4) * 136;
                    float w0 = ddsN[kt + kb + t4];
                    float w1 = ddsN[kt + kb + t4 + 4];
                    uint32_t af[2][4];
                    #pragma unroll
                    for (int mi = 0; mi < 2; mi++) {
                        int mH = mi * 16;
                        af[mi][0] = to_tf32(r0[32 + mH + g] * w0);
                        af[mi][1] = to_tf32(r0[32 + mH + g + 8] * w0);
                        af[mi][2] = to_tf32(r1[32 + mH + g] * w1);
                        af[mi][3] = to_tf32(r1[32 + mH + g + 8] * w1);
                    }
                    #pragma unroll
                    for (int nt = 0; nt < 2; nt++) {
                        int nb = nH + nt * 8;
                        uint32_t b0 = to_tf32(r0[nb + g]);
                        uint32_t b1 = to_tf32(r1[nb + g]);
                        MMA_TF32(hacc[0][nt], af[0][0], af[0][1], af[0][2], af[0][3], b0, b1);
                        MMA_TF32(hacc[1][nt], af[1][0], af[1][1], af[1][2], af[1][3], b0, b1);
                    }
                }
                __syncthreads();
            }
            float* HsS = Hs2 + s5 * 2080;
            #pragma unroll
            for (int mi = 0; mi < 2; mi++)
                #pragma unroll
                for (int nt = 0; nt < 2; nt++) {
                    int j0 = nH + nt * 8 + t4 * 2;
                    int row = mi * 16 + g;
                    HsS[row * 65 + j0]           += hacc[mi][nt][0];
                    HsS[row * 65 + j0 + 1]       += hacc[mi][nt][1];
                    HsS[(row + 8) * 65 + j0]     += hacc[mi][nt][2];
                    HsS[(row + 8) * 65 + j0 + 1] += hacc[mi][nt][3];
                }
        }
        __syncthreads();
    }

    // ---- Solve (2 warps, one per sample) ----
    float* Sv = Mt2;   // dead (2x1088 <= 8704)
    if (tid < 64) {
        int ws = tid >> 5, ln = tid & 31;
        const float* HsS = Hs2 + ws * 2080;
        float* SvN = Sv + ws * 1088;
        const float* qd = xs + ws * 64 + 32;
        float r = HsS[ln * 65 + 64];   // gsA
        #pragma unroll 8
        for (int j = 0; j < 32; j++) r -= HsS[ln * 65 + j] * qd[j];
        #pragma unroll 8
        for (int j = 0; j < 32; j++)
            SvN[ln * 34 + j] = HsS[ln * 65 + 32 + j] + ((ln == j) ? 2.0f : 0.0f);
        SvN[ln * 34 + 32] = r;
        __syncwarp();

        for (int p = 0; p < 32; p++) {
            float v = (ln >= p) ? fabsf(SvN[ln * 34 + p]) : -1.0f;
            int idx = ln;
            #pragma unroll
            for (int off = 16; off; off >>= 1) {
                float v2 = __shfl_xor_sync(0xffffffffu, v, off);
                int   i2 = __shfl_xor_sync(0xffffffffu, idx, off);
                if (v2 > v || (v2 == v && i2 < idx)) { v = v2; idx = i2; }
            }
            if (idx != p) {
                float t1 = SvN[p * 34 + ln];
                SvN[p * 34 + ln]   = SvN[idx * 34 + ln];
                SvN[idx * 34 + ln] = t1;
                if (ln == 0) {
                    float t2 = SvN[p * 34 + 32];
                    SvN[p * 34 + 32]   = SvN[idx * 34 + 32];
                    SvN[idx * 34 + 32] = t2;
                }
            }
            __syncwarp();
            float pinvv = 1.0f / SvN[p * 34 + p];
            if (ln != p) {
                float f = SvN[ln * 34 + p] * pinvv;
                for (int c = p; c < 33; c++)
                    SvN[ln * 34 + c] -= f * SvN[p * 34 + c];
            }
            __syncwarp();
        }
        float qdd = SvN[ln * 34 + 32] / SvN[ln * 34 + ln];
        int sample = b * 2 + ws;
        out[sample * 64 + ln]      = xs[ws * 64 + 32 + ln];
        out[sample * 64 + 32 + ln] = qdd;
    }
}

extern "C" void kernel_launch(void* const* d_in, const int* in_sizes, int n_in,
                              void* d_out, int out_size)
{
    const float* x   = (const float*)d_in[0];
    const float* W1m = (const float*)d_in[1];
    const float* b1m = (const float*)d_in[2];
    const float* W2m = (const float*)d_in[3];
    const float* b2m = (const float*)d_in[4];
    const float* W3m = (const float*)d_in[5];
    const float* W1q = (const float*)d_in[6];
    const float* b1q = (const float*)d_in[7];
    const float* W2q = (const float*)d_in[8];
    const float* b2q = (const float*)d_in[9];
    const float* W3q = (const float*)d_in[10];
    float* out = (float*)d_out;

    int B = in_sizes[0] / 64;

    prep_kernel<<<256, 256>>>(W1m, W2m, W1q, W2q);
    cudaFuncSetAttribute(lnn_kernel, cudaFuncAttributeMaxDynamicSharedMemorySize, SMEM_BYTES);
    lnn_kernel<<<B / 2, 256, SMEM_BYTES>>>(x, W1m, b1m, W2m, b2m, W3m,
                                           W1q, b1q, W2q, b2q, W3q, out);
}

// round 14
// speedup vs baseline: 1.2810x; 1.2810x over previous
#include <cuda_runtime.h>
#include <math.h>
#include <stdint.h>

#define HD 256
#define DD 64

__device__ float g_W1T[2 * DD * HD];   // [pass][(j*64 + m)]
__device__ float g_W2T[2 * HD * HD];   // [pass][(k*256 + j)]

__global__ void prep_kernel(const float* __restrict__ W1m, const float* __restrict__ W2m,
                            const float* __restrict__ W1q, const float* __restrict__ W2q)
{
    int t = blockIdx.x * blockDim.x + threadIdx.x;
    if (t < DD * HD) {
        int j = t >> 6, m = t & 63;
        g_W1T[t]           = W1m[m * HD + j];
        g_W1T[DD * HD + t] = W1q[m * HD + j];
    }
    if (t < HD * HD) {
        int k = t >> 8, j = t & 255;
        g_W2T[t]           = W2m[j * HD + k];
        g_W2T[HD * HD + t] = W2q[j * HD + k];
    }
}

__device__ __forceinline__ uint32_t to_tf32(float x) {
    uint32_t r;
    asm("cvt.rna.tf32.f32 %0, %1;" : "=r"(r) : "f"(x));
    return r;
}

__device__ __forceinline__ uint32_t pack_bf16x2(float lo, float hi) {
    uint32_t r;
    asm("cvt.rn.bf16x2.f32 %0, %1, %2;" : "=r"(r) : "f"(hi), "f"(lo));
    return r;
}

#define MMA_TF32(acc, a0, a1, a2, a3, b0, b1)                                   \
    asm volatile(                                                               \
        "mma.sync.aligned.m16n8k8.row.col.f32.tf32.tf32.f32 "                   \
        "{%0,%1,%2,%3}, {%4,%5,%6,%7}, {%8,%9}, {%0,%1,%2,%3};\n"               \
        : "+f"(acc[0]), "+f"(acc[1]), "+f"(acc[2]), "+f"(acc[3])                \
        : "r"(a0), "r"(a1), "r"(a2), "r"(a3), "r"(b0), "r"(b1))

#define MMA_BF16(acc, a0, a1, a2, a3, b0, b1)                                   \
    asm volatile(                                                               \
        "mma.sync.aligned.m16n8k16.row.col.f32.bf16.bf16.f32 "                  \
        "{%0,%1,%2,%3}, {%4,%5,%6,%7}, {%8,%9}, {%0,%1,%2,%3};\n"               \
        : "+f"(acc[0]), "+f"(acc[1]), "+f"(acc[2]), "+f"(acc[3])                \
        : "r"(a0), "r"(a1), "r"(a2), "r"(a3), "r"(b0), "r"(b1))

// Shared memory (floats), NS=2 samples per CTA (R12 structure, bf16 stage-5 tiles):
//   Mt2   [2][128][68] 17408  M n-chunk (128 n) per sample (k-major); Sv in solve
//   Tile5 3072: Asb = 128 m' x 12 uint (bf16x2 A tile), Bsb = 128 n x 12 uint
//               (also aliased as H1's fp32 W1T tile, pitch 136, 2176 floats)
//   Hs2   [2][32][65]  4160   H rows 32..63 per sample; col 64 = gsA (rows 0..31)
//   vA/vB/vC/vD/vE 512 each
//   xs 128
// Total 27,328 floats = 109,312 B -> 2 CTAs/SM.
#define SMEM_FLOATS (17408 + 3072 + 4160 + 5*512 + 128)
#define SMEM_BYTES  (SMEM_FLOATS * 4)

__global__ __launch_bounds__(256, 2)
void lnn_kernel(const float* __restrict__ x,
                const float* __restrict__ W1m, const float* __restrict__ b1m,
                const float* __restrict__ W2m, const float* __restrict__ b2m,
                const float* __restrict__ W3m,
                const float* __restrict__ W1q, const float* __restrict__ b1q,
                const float* __restrict__ W2q, const float* __restrict__ b2q,
                const float* __restrict__ W3q,
                float* __restrict__ out)
{
    extern __shared__ float sm[];
    float* Mt2   = sm;                // 17408 (pitch 68; sample stride 8704)
    float* Tile5 = Mt2 + 17408;       // 3072 (bf16 tiles / H1 fp32 tile)
    float* Hs2   = Tile5 + 3072;      // 4160 (pitch 65; col 64 = gsA)
    float* vA    = Hs2 + 4160;        // 512
    float* vB    = vA + 512;          // 512
    float* vC    = vB + 512;          // 512
    float* vD    = vC + 512;          // 512
    float* vE    = vD + 512;          // 512
    float* xs    = vE + 512;          // 128

    uint32_t* Asb = (uint32_t*)Tile5;         // 1536 uint (128 x 12)
    uint32_t* Bsb = (uint32_t*)(Tile5 + 1536);// 1536 uint (128 x 12)

    const int tid = threadIdx.x;
    const int b   = blockIdx.x;      // samples 2b, 2b+1

    for (int q = tid; q < 4160; q += 256) Hs2[q] = 0.0f;
    if (tid < 128) xs[tid] = x[b * 128 + tid];
    __syncthreads();

    const int wid = tid >> 5, lane = tid & 31;
    const int g = lane >> 2, t4 = lane & 3;

    #pragma unroll 1
    for (int pass = 0; pass < 2; pass++) {
        const float* W1  = pass ? W1q : W1m;
        const float* b1  = pass ? b1q : b1m;
        const float* W2  = pass ? W2q : W2m;
        const float* b2  = pass ? b2q : b2m;
        const float* W3  = pass ? W3q : W3m;
        const float* W1T = g_W1T + pass * (DD * HD);
        const float* W2T = g_W2T + pass * (HD * HD);

        // ---- Stage 1: z1 = x W1 + b1 (both samples); h1, a, s ----
        {
            int j = tid;
            float bv = b1[j];
            float p0 = bv, p1 = 0.f, p2 = 0.f, p3 = 0.f;
            float q0 = bv, q1 = 0.f, q2 = 0.f, q3 = 0.f;
            const float4* x0 = (const float4*)xs;
            const float4* x1 = (const float4*)(xs + 64);
            #pragma unroll 4
            for (int i4 = 0; i4 < 16; i4++) {
                int i = i4 * 4;
                float w0 = W1[(i + 0) * HD + j];
                float w1 = W1[(i + 1) * HD + j];
                float w2 = W1[(i + 2) * HD + j];
                float w3 = W1[(i + 3) * HD + j];
                float4 u0 = x0[i4], u1 = x1[i4];
                p0 = fmaf(u0.x, w0, p0); q0 = fmaf(u1.x, w0, q0);
                p1 = fmaf(u0.y, w1, p1); q1 = fmaf(u1.y, w1, q1);
                p2 = fmaf(u0.z, w2, p2); q2 = fmaf(u1.z, w2, q2);
                p3 = fmaf(u0.w, w3, p3); q3 = fmaf(u1.w, w3, q3);
            }
            float z0v = (p0 + p1) + (p2 + p3);
            float z1v = (q0 + q1) + (q2 + q3);
            #pragma unroll
            for (int ns = 0; ns < 2; ns++) {
                float z = ns ? z1v : z0v;
                float h, a, s;
                if (pass == 0) {
                    float sg = 1.0f / (1.0f + __expf(-z));
                    h = fmaxf(z, 0.0f) + log1pf(__expf(-fabsf(z)));
                    a = sg;
                    s = sg * (1.0f - sg);
                } else {
                    float t = tanhf(0.5f * z);
                    float o = 1.0f - t * t;
                    h = z * t;
                    a = fmaf(0.5f * z, o, t);
                    s = o * (1.0f - 0.5f * z * t);
                }
                vA[ns * 256 + j] = h;
                vC[ns * 256 + j] = a;
                vD[ns * 256 + j] = s;
            }
        }
        __syncthreads();

        // ---- Stage 2: z2 = h1 W2 + b2 ; c, e ----
        {
            int k = tid;
            float bv = b2[k];
            float p0 = bv, p1 = 0.f, p2 = 0.f, p3 = 0.f;
            float q0 = bv, q1 = 0.f, q2 = 0.f, q3 = 0.f;
            const float4* h0 = (const float4*)vA;
            const float4* h1v = (const float4*)(vA + 256);
            #pragma unroll 4
            for (int l4 = 0; l4 < 64; l4++) {
                int l = l4 * 4;
                float w0 = W2[(l + 0) * HD + k];
                float w1 = W2[(l + 1) * HD + k];
                float w2 = W2[(l + 2) * HD + k];
                float w3 = W2[(l + 3) * HD + k];
                float4 u0 = h0[l4], u1 = h1v[l4];
                p0 = fmaf(u0.x, w0, p0); q0 = fmaf(u1.x, w0, q0);
                p1 = fmaf(u0.y, w1, p1); q1 = fmaf(u1.y, w1, q1);
                p2 = fmaf(u0.z, w2, p2); q2 = fmaf(u1.z, w2, q2);
                p3 = fmaf(u0.w, w3, p3); q3 = fmaf(u1.w, w3, q3);
            }
            float z0v = (p0 + p1) + (p2 + p3);
            float z1v = (q0 + q1) + (q2 + q3);
            float w3v = W3[k];
            #pragma unroll
            for (int ns = 0; ns < 2; ns++) {
                float z = ns ? z1v : z0v;
                float a, s;
                if (pass == 0) {
                    float sg = 1.0f / (1.0f + __expf(-z));
                    a = sg;
                    s = sg * (1.0f - sg);
                } else {
                    float t = tanhf(0.5f * z);
                    float o = 1.0f - t * t;
                    a = fmaf(0.5f * z, o, t);
                    s = o * (1.0f - 0.5f * z * t);
                }
                vB[ns * 256 + k] = a * w3v;
                vE[ns * 256 + k] = s * w3v;
            }
        }
        __syncthreads();

        // ---- Stage 3: u = W2 c ; dds = s*u, aus = a*u ----
        {
            int j = tid;
            float p0 = 0.f, p1 = 0.f, p2 = 0.f, p3 = 0.f;
            float q0 = 0.f, q1 = 0.f, q2 = 0.f, q3 = 0.f;
            const float4* c0 = (const float4*)vB;
            const float4* c1 = (const float4*)(vB + 256);
            #pragma unroll 4
            for (int k4 = 0; k4 < 64; k4++) {
                int k = k4 * 4;
                float w0 = W2T[(k + 0) * HD + j];
                float w1 = W2T[(k + 1) * HD + j];
                float w2 = W2T[(k + 2) * HD + j];
                float w3 = W2T[(k + 3) * HD + j];
                float4 u0 = c0[k4], u1 = c1[k4];
                p0 = fmaf(u0.x, w0, p0); q0 = fmaf(u1.x, w0, q0);
                p1 = fmaf(u0.y, w1, p1); q1 = fmaf(u1.y, w1, q1);
                p2 = fmaf(u0.z, w2, p2); q2 = fmaf(u1.z, w2, q2);
                p3 = fmaf(u0.w, w3, p3); q3 = fmaf(u1.w, w3, q3);
            }
            float u0v = (p0 + p1) + (p2 + p3);
            float u1v = (q0 + q1) + (q2 + q3);
            float s0 = vD[j], s1 = vD[256 + j];
            float a0 = vC[j], a1 = vC[256 + j];
            vD[j]       = s0 * u0v;  vD[256 + j] = s1 * u1v;
            vA[j]       = a0 * u0v;  vA[256 + j] = a1 * u1v;
        }
        __syncthreads();

        // ---- Stage 4: g = W1 (a*u), 4-way j-split, both samples ----
        {
            int m = tid & 63, part = tid >> 6;
            const float* W1Tp = W1T + part * 64 * 64;
            const float4* a0 = (const float4*)(vA + part * 64);
            const float4* a1 = (const float4*)(vA + 256 + part * 64);
            float p0 = 0.f, p1 = 0.f, p2 = 0.f, p3 = 0.f;
            float q0 = 0.f, q1 = 0.f, q2 = 0.f, q3 = 0.f;
            #pragma unroll 4
            for (int j4 = 0; j4 < 16; j4++) {
                int jj = j4 * 4;
                float w0 = W1Tp[(jj + 0) * 64 + m];
                float w1 = W1Tp[(jj + 1) * 64 + m];
                float w2 = W1Tp[(jj + 2) * 64 + m];
                float w3 = W1Tp[(jj + 3) * 64 + m];
                float4 u0 = a0[j4], u1 = a1[j4];
                p0 = fmaf(w0, u0.x, p0); q0 = fmaf(w0, u1.x, q0);
                p1 = fmaf(w1, u0.y, p1); q1 = fmaf(w1, u1.y, q1);
                p2 = fmaf(w2, u0.z, p2); q2 = fmaf(w2, u1.z, q2);
                p3 = fmaf(w3, u0.w, p3); q3 = fmaf(w3, u1.w, q3);
            }
            float g0 = (p0 + p1) + (p2 + p3);
            float g1 = (q0 + q1) + (q2 + q3);
            vB[part * 64 + m]       = g0;   // ccs dead after stage 3 sync
            vB[256 + part * 64 + m] = g1;
        }
        __syncthreads();
        // Only g[0..31] feeds the solve; Hs2 has 32 rows per sample.
        if (tid < 64) {
            int ns = tid >> 5, mm = tid & 31;
            const float* gp = vB + ns * 256;
            Hs2[ns * 2080 + mm * 65 + 64] += gp[mm] + gp[64 + mm] + gp[128 + mm] + gp[192 + mm];
        }

        // ---- Stage 5+H2 fused per n-chunk of 128 (bf16 TENSOR) ----
        // Warp tiling 2m x 8n: warp = (m-pair mp, n-half nh).
        const int mp  = wid & 3;           // m rows mp*32 .. +31 (m' = 2x64)
        const int nh  = wid >> 2;          // n cols nh*64 .. +63 (8 n-tiles)
        const int s5  = wid & 1;           // H-phase sample
        const int nH  = (wid >> 1) * 16;   // H-phase col group
        const int mq   = tid & 127;        // staging row (m' or n)
        const int half = tid >> 7;         // staging j-pair half (0..3 or 4..7)
        const int smp5 = mq >> 6, ml5 = mq & 63;

        #pragma unroll 1
        for (int ktile = 0; ktile < 2; ktile++) {
            float acc[2][8][4];
            #pragma unroll
            for (int mi = 0; mi < 2; mi++)
                #pragma unroll
                for (int i = 0; i < 8; i++)
                    #pragma unroll
                    for (int j = 0; j < 4; j++) acc[mi][i][j] = 0.f;

            #pragma unroll 1
            for (int jt = 0; jt < 256; jt += 16) {
                // stage A: Asb[m'][jp] = bf16x2(a_j W1T[j][m'], j pair), pitch 12
                {
                    uint32_t pk[4];
                    #pragma unroll
                    for (int p = 0; p < 4; p++) {
                        int j0 = jt + (half * 4 + p) * 2;
                        float lo = W1T[j0 * 64 + ml5]       * vC[smp5 * 256 + j0];
                        float hi = W1T[(j0 + 1) * 64 + ml5] * vC[smp5 * 256 + j0 + 1];
                        pk[p] = pack_bf16x2(lo, hi);
                    }
                    *(uint4*)(Asb + mq * 12 + half * 4) = make_uint4(pk[0], pk[1], pk[2], pk[3]);
                }
                // stage B: Bsb[n][jp] = bf16x2(W2[j][n] pair), pitch 12
                {
                    uint32_t pk[4];
                    #pragma unroll
                    for (int p = 0; p < 4; p++) {
                        int j0 = jt + (half * 4 + p) * 2;
                        float lo = W2[j0 * HD + ktile * 128 + mq];
                        float hi = W2[(j0 + 1) * HD + ktile * 128 + mq];
                        pk[p] = pack_bf16x2(lo, hi);
                    }
                    *(uint4*)(Bsb + mq * 12 + half * 4) = make_uint4(pk[0], pk[1], pk[2], pk[3]);
                }
                __syncthreads();

                // one k16 step covers the 16-j tile
                {
                    uint32_t af[2][4];
                    #pragma unroll
                    for (int mi = 0; mi < 2; mi++) {
                        int mb = mp * 32 + mi * 16;
                        af[mi][0] = Asb[(mb + g) * 12 + t4];
                        af[mi][1] = Asb[(mb + g + 8) * 12 + t4];
                        af[mi][2] = Asb[(mb + g) * 12 + t4 + 4];
                        af[mi][3] = Asb[(mb + g + 8) * 12 + t4 + 4];
                    }
                    #pragma unroll
                    for (int nt = 0; nt < 8; nt++) {
                        int nb = nh * 64 + nt * 8;
                        uint32_t b0 = Bsb[(nb + g) * 12 + t4];
                        uint32_t b1 = Bsb[(nb + g) * 12 + t4 + 4];
                        MMA_BF16(acc[0][nt], af[0][0], af[0][1], af[0][2], af[0][3], b0, b1);
                        MMA_BF16(acc[1][nt], af[1][0], af[1][1], af[1][2], af[1][3], b0, b1);
                    }
                }
                __syncthreads();
            }

            // epilogue: Mt2[sample][n][m] (k-major per sample)
            {
                int smp = mp >> 1;
                float* Mbase = Mt2 + smp * 8704;
                #pragma unroll
                for (int mi = 0; mi < 2; mi++) {
                    int mloc = (mp & 1) * 32 + mi * 16 + g;
                    #pragma unroll
                    for (int nt = 0; nt < 8; nt++) {
                        int n0 = nh * 64 + nt * 8 + t4 * 2;
                        Mbase[n0 * 68 + mloc]           = acc[mi][nt][0];
                        Mbase[(n0 + 1) * 68 + mloc]     = acc[mi][nt][1];
                        Mbase[n0 * 68 + mloc + 8]       = acc[mi][nt][2];
                        Mbase[(n0 + 1) * 68 + mloc + 8] = acc[mi][nt][3];
                    }
                }
            }
            __syncthreads();

            // H2 over this 128-k chunk: Hs2[s5] += sum_k e_k M[k][32+i] M[k][j]
            {
                float hacc[2][2][4];
                #pragma unroll
                for (int a = 0; a < 2; a++)
                    #pragma unroll
                    for (int c = 0; c < 2; c++)
                        #pragma unroll
                        for (int d = 0; d < 4; d++) hacc[a][c][d] = 0.f;

                const float* eesN = vE + s5 * 256 + ktile * 128;
                #pragma unroll 2
                for (int kk = 0; kk < 128; kk += 8) {
                    const float* r0 = Mt2 + s5 * 8704 + (kk + t4) * 68;
                    const float* r1 = r0 + 4 * 68;
                    float w0 = eesN[kk + t4];
                    float w1 = eesN[kk + t4 + 4];
                    uint32_t af[2][4];
                    #pragma unroll
                    for (int mi = 0; mi < 2; mi++) {
                        int mH = mi * 16;
                        af[mi][0] = to_tf32(r0[32 + mH + g] * w0);
                        af[mi][1] = to_tf32(r0[32 + mH + g + 8] * w0);
                        af[mi][2] = to_tf32(r1[32 + mH + g] * w1);
                        af[mi][3] = to_tf32(r1[32 + mH + g + 8] * w1);
                    }
                    #pragma unroll
                    for (int nt = 0; nt < 2; nt++) {
                        int nb = nH + nt * 8;
                        uint32_t b0 = to_tf32(r0[nb + g]);
                        uint32_t b1 = to_tf32(r1[nb + g]);
                        MMA_TF32(hacc[0][nt], af[0][0], af[0][1], af[0][2], af[0][3], b0, b1);
                        MMA_TF32(hacc[1][nt], af[1][0], af[1][1], af[1][2], af[1][3], b0, b1);
                    }
                }
                float* HsS = Hs2 + s5 * 2080;
                #pragma unroll
                for (int mi = 0; mi < 2; mi++)
                    #pragma unroll
                    for (int nt = 0; nt < 2; nt++) {
                        int j0 = nH + nt * 8 + t4 * 2;
                        int row = mi * 16 + g;
                        HsS[row * 65 + j0]           += hacc[mi][nt][0];
                        HsS[row * 65 + j0 + 1]       += hacc[mi][nt][1];
                        HsS[(row + 8) * 65 + j0]     += hacc[mi][nt][2];
                        HsS[(row + 8) * 65 + j0 + 1] += hacc[mi][nt][3];
                    }
            }
            __syncthreads();
        }

        // ---- H1 (TENSOR, tf32): Hs2[s] += sum_k d_k W1T[k][32+i] W1T[k][j] ----
        // fp32 W1T tile staged in Tile5 (pitch 136)
        {
            float* H1t = Tile5;
            const float4* W1Tv = (const float4*)W1T;
            float hacc[2][2][4];
            #pragma unroll
            for (int a = 0; a < 2; a++)
                #pragma unroll
                for (int c = 0; c < 2; c++)
                    #pragma unroll
                    for (int d = 0; d < 4; d++) hacc[a][c][d] = 0.f;

            const float* ddsN = vD + s5 * 256;
            #pragma unroll 1
            for (int kt = 0; kt < 256; kt += 16) {
                {
                    int kl = tid >> 4, m4 = tid & 15;
                    *(float4*)(H1t + kl * 136 + m4 * 4) = W1Tv[(kt + kl) * 16 + m4];
                }
                __syncthreads();
                #pragma unroll
                for (int s = 0; s < 2; s++) {
                    int kb = s * 8;
                    const float* r0 = H1t + (kb + t4) * 136;
                    const float* r1 = H1t + (kb + t4 + 4) * 136;
                    float w0 = ddsN[kt + kb + t4];
                    float w1 = ddsN[kt + kb + t4 + 4];
                    uint32_t af[2][4];
                    #pragma unroll
                    for (int mi = 0; mi < 2; mi++) {
                        int mH = mi * 16;
                        af[mi][0] = to_tf32(r0[32 + mH + g] * w0);
                        af[mi][1] = to_tf32(r0[32 + mH + g + 8] * w0);
                        af[mi][2] = to_tf32(r1[32 + mH + g] * w1);
                        af[mi][3] = to_tf32(r1[32 + mH + g + 8] * w1);
                    }
                    #pragma unroll
                    for (int nt = 0; nt < 2; nt++) {
                        int nb = nH + nt * 8;
                        uint32_t b0 = to_tf32(r0[nb + g]);
                        uint32_t b1 = to_tf32(r1[nb + g]);
                        MMA_TF32(hacc[0][nt], af[0][0], af[0][1], af[0][2], af[0][3], b0, b1);
                        MMA_TF32(hacc[1][nt], af[1][0], af[1][1], af[1][2], af[1][3], b0, b1);
                    }
                }
                __syncthreads();
            }
            float* HsS = Hs2 + s5 * 2080;
            #pragma unroll
            for (int mi = 0; mi < 2; mi++)
                #pragma unroll
                for (int nt = 0; nt < 2; nt++) {
                    int j0 = nH + nt * 8 + t4 * 2;
                    int row = mi * 16 + g;
                    HsS[row * 65 + j0]           += hacc[mi][nt][0];
                    HsS[row * 65 + j0 + 1]       += hacc[mi][nt][1];
                    HsS[(row + 8) * 65 + j0]     += hacc[mi][nt][2];
                    HsS[(row + 8) * 65 + j0 + 1] += hacc[mi][nt][3];
                }
        }
        __syncthreads();
    }

    // ---- Solve (2 warps, one per sample) ----
    float* Sv = Mt2;   // dead
    if (tid < 64) {
        int ws = tid >> 5, ln = tid & 31;
        const float* HsS = Hs2 + ws * 2080;
        float* SvN = Sv + ws * 1088;
        const float* qd = xs + ws * 64 + 32;
        float r = HsS[ln * 65 + 64];   // gsA
        #pragma unroll 8
        for (int j = 0; j < 32; j++) r -= HsS[ln * 65 + j] * qd[j];
        #pragma unroll 8
        for (int j = 0; j < 32; j++)
            SvN[ln * 34 + j] = HsS[ln * 65 + 32 + j] + ((ln == j) ? 2.0f : 0.0f);
        SvN[ln * 34 + 32] = r;
        __syncwarp();

        for (int p = 0; p < 32; p++) {
            float v = (ln >= p) ? fabsf(SvN[ln * 34 + p]) : -1.0f;
            int idx = ln;
            #pragma unroll
            for (int off = 16; off; off >>= 1) {
                float v2 = __shfl_xor_sync(0xffffffffu, v, off);
                int   i2 = __shfl_xor_sync(0xffffffffu, idx, off);
                if (v2 > v || (v2 == v && i2 < idx)) { v = v2; idx = i2; }
            }
            if (idx != p) {
                float t1 = SvN[p * 34 + ln];
                SvN[p * 34 + ln]   = SvN[idx * 34 + ln];
                SvN[idx * 34 + ln] = t1;
                if (ln == 0) {
                    float t2 = SvN[p * 34 + 32];
                    SvN[p * 34 + 32]   = SvN[idx * 34 + 32];
                    SvN[idx * 34 + 32] = t2;
                }
            }
            __syncwarp();
            float pinvv = 1.0f / SvN[p * 34 + p];
            if (ln != p) {
                float f = SvN[ln * 34 + p] * pinvv;
                for (int c = p; c < 33; c++)
                    SvN[ln * 34 + c] -= f * SvN[p * 34 + c];
            }
            __syncwarp();
        }
        float qdd = SvN[ln * 34 + 32] / SvN[ln * 34 + ln];
        int sample = b * 2 + ws;
        out[sample * 64 + ln]      = xs[ws * 64 + 32 + ln];
        out[sample * 64 + 32 + ln] = qdd;
    }
}

extern "C" void kernel_launch(void* const* d_in, const int* in_sizes, int n_in,
                              void* d_out, int out_size)
{
    const float* x   = (const float*)d_in[0];
    const float* W1m = (const float*)d_in[1];
    const float* b1m = (const float*)d_in[2];
    const float* W2m = (const float*)d_in[3];
    const float* b2m = (const float*)d_in[4];
    const float* W3m = (const float*)d_in[5];
    const float* W1q = (const float*)d_in[6];
    const float* b1q = (const float*)d_in[7];
    const float* W2q = (const float*)d_in[8];
    const float* b2q = (const float*)d_in[9];
    const float* W3q = (const float*)d_in[10];
    float* out = (float*)d_out;

    int B = in_sizes[0] / 64;

    prep_kernel<<<256, 256>>>(W1m, W2m, W1q, W2q);
    cudaFuncSetAttribute(lnn_kernel, cudaFuncAttributeMaxDynamicSharedMemorySize, SMEM_BYTES);
    lnn_kernel<<<B / 2, 256, SMEM_BYTES>>>(x, W1m, b1m, W2m, b2m, W3m,
                                           W1q, b1q, W2q, b2q, W3q, out);
}

// round 15
// speedup vs baseline: 1.3979x; 1.0912x over previous
#include <cuda_runtime.h>
#include <math.h>
#include <stdint.h>

#define HD 256
#define DD 64

__device__ float g_W1T[2 * DD * HD];   // [pass][(j*64 + m)]
__device__ float g_W2T[2 * HD * HD];   // [pass][(k*256 + j)]

__global__ void prep_kernel(const float* __restrict__ W1m, const float* __restrict__ W2m,
                            const float* __restrict__ W1q, const float* __restrict__ W2q)
{
    int t = blockIdx.x * blockDim.x + threadIdx.x;
    if (t < DD * HD) {
        int j = t >> 6, m = t & 63;
        g_W1T[t]           = W1m[m * HD + j];
        g_W1T[DD * HD + t] = W1q[m * HD + j];
    }
    if (t < HD * HD) {
        int k = t >> 8, j = t & 255;
        g_W2T[t]           = W2m[j * HD + k];
        g_W2T[HD * HD + t] = W2q[j * HD + k];
    }
}

__device__ __forceinline__ uint32_t to_tf32(float x) {
    uint32_t r;
    asm("cvt.rna.tf32.f32 %0, %1;" : "=r"(r) : "f"(x));
    return r;
}

__device__ __forceinline__ uint32_t pack_bf16x2(float lo, float hi) {
    uint32_t r;
    asm("cvt.rn.bf16x2.f32 %0, %1, %2;" : "=r"(r) : "f"(hi), "f"(lo));
    return r;
}

__device__ __forceinline__ uint32_t hmul2_bf16(uint32_t a, uint32_t b) {
    uint32_t r;
    asm("mul.rn.bf16x2 %0, %1, %2;" : "=r"(r) : "r"(a), "r"(b));
    return r;
}

#define MMA_TF32(acc, a0, a1, a2, a3, b0, b1)                                   \
    asm volatile(                                                               \
        "mma.sync.aligned.m16n8k8.row.col.f32.tf32.tf32.f32 "                   \
        "{%0,%1,%2,%3}, {%4,%5,%6,%7}, {%8,%9}, {%0,%1,%2,%3};\n"               \
        : "+f"(acc[0]), "+f"(acc[1]), "+f"(acc[2]), "+f"(acc[3])                \
        : "r"(a0), "r"(a1), "r"(a2), "r"(a3), "r"(b0), "r"(b1))

#define MMA_BF16(acc, a0, a1, a2, a3, b0, b1)                                   \
    asm volatile(                                                               \
        "mma.sync.aligned.m16n8k16.row.col.f32.bf16.bf16.f32 "                  \
        "{%0,%1,%2,%3}, {%4,%5,%6,%7}, {%8,%9}, {%0,%1,%2,%3};\n"               \
        : "+f"(acc[0]), "+f"(acc[1]), "+f"(acc[2]), "+f"(acc[3])                \
        : "r"(a0), "r"(a1), "r"(a2), "r"(a3), "r"(b0), "r"(b1))

// Shared memory (floats), NS=2 samples per CTA:
//   MtB   [2][128][72] 18432  M packed bf16x2 along n-pairs (kp = n/2), FULL 256 n;
//                             pitch 72 (bank-clean); Sv (fp32) in solve
//   Tile5 3072: Asb 128x12 uint bf16x2 A-tile, Bsb 128x12 uint B-tile
//               (aliased as H1 fp32 W1T tile pitch 136, 2176 <= 3072)
//   Hs2   [2][32][65]  4160   H rows 32..63 per sample; col 64 = gsA (rows 0..31)
//   vA/vB/vC/vD/vE 512 each
//   xs 128
// Total 28,352 floats = 113,408 B -> 2 CTAs/SM.
#define SMEM_FLOATS (18432 + 3072 + 4160 + 5*512 + 128)
#define SMEM_BYTES  (SMEM_FLOATS * 4)

__global__ __launch_bounds__(256, 2)
void lnn_kernel(const float* __restrict__ x,
                const float* __restrict__ W1m, const float* __restrict__ b1m,
                const float* __restrict__ W2m, const float* __restrict__ b2m,
                const float* __restrict__ W3m,
                const float* __restrict__ W1q, const float* __restrict__ b1q,
                const float* __restrict__ W2q, const float* __restrict__ b2q,
                const float* __restrict__ W3q,
                float* __restrict__ out)
{
    extern __shared__ float sm[];
    float* MtBf  = sm;                // 18432 (uint view below)
    float* Tile5 = MtBf + 18432;      // 3072
    float* Hs2   = Tile5 + 3072;      // 4160 (pitch 65; col 64 = gsA)
    float* vA    = Hs2 + 4160;        // 512
    float* vB    = vA + 512;          // 512
    float* vC    = vB + 512;          // 512
    float* vD    = vC + 512;          // 512
    float* vE    = vD + 512;          // 512
    float* xs    = vE + 512;          // 128

    uint32_t* MtB = (uint32_t*)MtBf;          // [2][128 kp][72]
    uint32_t* Asb = (uint32_t*)Tile5;         // 1536 uint (128 x 12)
    uint32_t* Bsb = (uint32_t*)(Tile5 + 1536);// 1536 uint (128 x 12)

    const int tid = threadIdx.x;
    const int b   = blockIdx.x;      // samples 2b, 2b+1

    for (int q = tid; q < 4160; q += 256) Hs2[q] = 0.0f;
    if (tid < 128) xs[tid] = x[b * 128 + tid];
    __syncthreads();

    const int wid = tid >> 5, lane = tid & 31;
    const int g = lane >> 2, t4 = lane & 3;

    #pragma unroll 1
    for (int pass = 0; pass < 2; pass++) {
        const float* W1  = pass ? W1q : W1m;
        const float* b1  = pass ? b1q : b1m;
        const float* W2  = pass ? W2q : W2m;
        const float* b2  = pass ? b2q : b2m;
        const float* W3  = pass ? W3q : W3m;
        const float* W1T = g_W1T + pass * (DD * HD);
        const float* W2T = g_W2T + pass * (HD * HD);

        // ---- Stage 1: z1 = x W1 + b1 (both samples); h1, a, s ----
        {
            int j = tid;
            float bv = b1[j];
            float p0 = bv, p1 = 0.f, p2 = 0.f, p3 = 0.f;
            float q0 = bv, q1 = 0.f, q2 = 0.f, q3 = 0.f;
            const float4* x0 = (const float4*)xs;
            const float4* x1 = (const float4*)(xs + 64);
            #pragma unroll 4
            for (int i4 = 0; i4 < 16; i4++) {
                int i = i4 * 4;
                float w0 = W1[(i + 0) * HD + j];
                float w1 = W1[(i + 1) * HD + j];
                float w2 = W1[(i + 2) * HD + j];
                float w3 = W1[(i + 3) * HD + j];
                float4 u0 = x0[i4], u1 = x1[i4];
                p0 = fmaf(u0.x, w0, p0); q0 = fmaf(u1.x, w0, q0);
                p1 = fmaf(u0.y, w1, p1); q1 = fmaf(u1.y, w1, q1);
                p2 = fmaf(u0.z, w2, p2); q2 = fmaf(u1.z, w2, q2);
                p3 = fmaf(u0.w, w3, p3); q3 = fmaf(u1.w, w3, q3);
            }
            float z0v = (p0 + p1) + (p2 + p3);
            float z1v = (q0 + q1) + (q2 + q3);
            #pragma unroll
            for (int ns = 0; ns < 2; ns++) {
                float z = ns ? z1v : z0v;
                float h, a, s;
                if (pass == 0) {
                    float sg = 1.0f / (1.0f + __expf(-z));
                    h = fmaxf(z, 0.0f) + log1pf(__expf(-fabsf(z)));
                    a = sg;
                    s = sg * (1.0f - sg);
                } else {
                    float t = tanhf(0.5f * z);
                    float o = 1.0f - t * t;
                    h = z * t;
                    a = fmaf(0.5f * z, o, t);
                    s = o * (1.0f - 0.5f * z * t);
                }
                vA[ns * 256 + j] = h;
                vC[ns * 256 + j] = a;
                vD[ns * 256 + j] = s;
            }
        }
        __syncthreads();

        // ---- Stage 2: z2 = h1 W2 + b2 ; c, e ----
        {
            int k = tid;
            float bv = b2[k];
            float p0 = bv, p1 = 0.f, p2 = 0.f, p3 = 0.f;
            float q0 = bv, q1 = 0.f, q2 = 0.f, q3 = 0.f;
            const float4* h0 = (const float4*)vA;
            const float4* h1v = (const float4*)(vA + 256);
            #pragma unroll 4
            for (int l4 = 0; l4 < 64; l4++) {
                int l = l4 * 4;
                float w0 = W2[(l + 0) * HD + k];
                float w1 = W2[(l + 1) * HD + k];
                float w2 = W2[(l + 2) * HD + k];
                float w3 = W2[(l + 3) * HD + k];
                float4 u0 = h0[l4], u1 = h1v[l4];
                p0 = fmaf(u0.x, w0, p0); q0 = fmaf(u1.x, w0, q0);
                p1 = fmaf(u0.y, w1, p1); q1 = fmaf(u1.y, w1, q1);
                p2 = fmaf(u0.z, w2, p2); q2 = fmaf(u1.z, w2, q2);
                p3 = fmaf(u0.w, w3, p3); q3 = fmaf(u1.w, w3, q3);
            }
            float z0v = (p0 + p1) + (p2 + p3);
            float z1v = (q0 + q1) + (q2 + q3);
            float w3v = W3[k];
            #pragma unroll
            for (int ns = 0; ns < 2; ns++) {
                float z = ns ? z1v : z0v;
                float a, s;
                if (pass == 0) {
                    float sg = 1.0f / (1.0f + __expf(-z));
                    a = sg;
                    s = sg * (1.0f - sg);
                } else {
                    float t = tanhf(0.5f * z);
                    float o = 1.0f - t * t;
                    a = fmaf(0.5f * z, o, t);
                    s = o * (1.0f - 0.5f * z * t);
                }
                vB[ns * 256 + k] = a * w3v;
                vE[ns * 256 + k] = s * w3v;
            }
        }
        __syncthreads();

        // ---- Stage 3: u = W2 c ; dds = s*u, aus = a*u ----
        {
            int j = tid;
            float p0 = 0.f, p1 = 0.f, p2 = 0.f, p3 = 0.f;
            float q0 = 0.f, q1 = 0.f, q2 = 0.f, q3 = 0.f;
            const float4* c0 = (const float4*)vB;
            const float4* c1 = (const float4*)(vB + 256);
            #pragma unroll 4
            for (int k4 = 0; k4 < 64; k4++) {
                int k = k4 * 4;
                float w0 = W2T[(k + 0) * HD + j];
                float w1 = W2T[(k + 1) * HD + j];
                float w2 = W2T[(k + 2) * HD + j];
                float w3 = W2T[(k + 3) * HD + j];
                float4 u0 = c0[k4], u1 = c1[k4];
                p0 = fmaf(u0.x, w0, p0); q0 = fmaf(u1.x, w0, q0);
                p1 = fmaf(u0.y, w1, p1); q1 = fmaf(u1.y, w1, q1);
                p2 = fmaf(u0.z, w2, p2); q2 = fmaf(u1.z, w2, q2);
                p3 = fmaf(u0.w, w3, p3); q3 = fmaf(u1.w, w3, q3);
            }
            float u0v = (p0 + p1) + (p2 + p3);
            float u1v = (q0 + q1) + (q2 + q3);
            float s0 = vD[j], s1 = vD[256 + j];
            float a0 = vC[j], a1 = vC[256 + j];
            vD[j]       = s0 * u0v;  vD[256 + j] = s1 * u1v;
            vA[j]       = a0 * u0v;  vA[256 + j] = a1 * u1v;
        }
        __syncthreads();

        // ---- Stage 4: g = W1 (a*u), 4-way j-split, both samples ----
        {
            int m = tid & 63, part = tid >> 6;
            const float* W1Tp = W1T + part * 64 * 64;
            const float4* a0 = (const float4*)(vA + part * 64);
            const float4* a1 = (const float4*)(vA + 256 + part * 64);
            float p0 = 0.f, p1 = 0.f, p2 = 0.f, p3 = 0.f;
            float q0 = 0.f, q1 = 0.f, q2 = 0.f, q3 = 0.f;
            #pragma unroll 4
            for (int j4 = 0; j4 < 16; j4++) {
                int jj = j4 * 4;
                float w0 = W1Tp[(jj + 0) * 64 + m];
                float w1 = W1Tp[(jj + 1) * 64 + m];
                float w2 = W1Tp[(jj + 2) * 64 + m];
                float w3 = W1Tp[(jj + 3) * 64 + m];
                float4 u0 = a0[j4], u1 = a1[j4];
                p0 = fmaf(w0, u0.x, p0); q0 = fmaf(w0, u1.x, q0);
                p1 = fmaf(w1, u0.y, p1); q1 = fmaf(w1, u1.y, q1);
                p2 = fmaf(w2, u0.z, p2); q2 = fmaf(w2, u1.z, q2);
                p3 = fmaf(w3, u0.w, p3); q3 = fmaf(w3, u1.w, q3);
            }
            float g0 = (p0 + p1) + (p2 + p3);
            float g1 = (q0 + q1) + (q2 + q3);
            vB[part * 64 + m]       = g0;   // ccs dead after stage 3 sync
            vB[256 + part * 64 + m] = g1;
        }
        __syncthreads();
        // Only g[0..31] feeds the solve; Hs2 has 32 rows per sample.
        if (tid < 64) {
            int ns = tid >> 5, mm = tid & 31;
            const float* gp = vB + ns * 256;
            Hs2[ns * 2080 + mm * 65 + 64] += gp[mm] + gp[64 + mm] + gp[128 + mm] + gp[192 + mm];
        }

        // ---- Stage 5 (bf16 TENSOR) per n-chunk of 128; M stored packed bf16x2 ----
        const int mp  = wid & 3;           // m rows mp*32 .. +31 (m' = 2x64)
        const int nh  = wid >> 2;          // n cols nh*64 .. +63 (8 n-tiles)
        const int s5  = wid & 1;           // H-phase sample
        const int nH  = (wid >> 1) * 16;   // H-phase col group
        const int mq   = tid & 127;        // staging row (m' or n)
        const int half = tid >> 7;         // staging j-pair half
        const int smp5 = mq >> 6, ml5 = mq & 63;

        #pragma unroll 1
        for (int ktile = 0; ktile < 2; ktile++) {
            float acc[2][8][4];
            #pragma unroll
            for (int mi = 0; mi < 2; mi++)
                #pragma unroll
                for (int i = 0; i < 8; i++)
                    #pragma unroll
                    for (int j = 0; j < 4; j++) acc[mi][i][j] = 0.f;

            #pragma unroll 1
            for (int jt = 0; jt < 256; jt += 16) {
                // stage A: Asb[m'][jp] = bf16x2(a_j W1T[j][m'] pair), pitch 12
                {
                    uint32_t pk[4];
                    #pragma unroll
                    for (int p = 0; p < 4; p++) {
                        int j0 = jt + (half * 4 + p) * 2;
                        float lo = W1T[j0 * 64 + ml5]       * vC[smp5 * 256 + j0];
                        float hi = W1T[(j0 + 1) * 64 + ml5] * vC[smp5 * 256 + j0 + 1];
                        pk[p] = pack_bf16x2(lo, hi);
                    }
                    *(uint4*)(Asb + mq * 12 + half * 4) = make_uint4(pk[0], pk[1], pk[2], pk[3]);
                }
                // stage B: Bsb[n][jp] = bf16x2(W2[j][n] pair), pitch 12
                {
                    uint32_t pk[4];
                    #pragma unroll
                    for (int p = 0; p < 4; p++) {
                        int j0 = jt + (half * 4 + p) * 2;
                        float lo = W2[j0 * HD + ktile * 128 + mq];
                        float hi = W2[(j0 + 1) * HD + ktile * 128 + mq];
                        pk[p] = pack_bf16x2(lo, hi);
                    }
                    *(uint4*)(Bsb + mq * 12 + half * 4) = make_uint4(pk[0], pk[1], pk[2], pk[3]);
                }
                __syncthreads();

                {
                    uint32_t af[2][4];
                    #pragma unroll
                    for (int mi = 0; mi < 2; mi++) {
                        int mb = mp * 32 + mi * 16;
                        af[mi][0] = Asb[(mb + g) * 12 + t4];
                        af[mi][1] = Asb[(mb + g + 8) * 12 + t4];
                        af[mi][2] = Asb[(mb + g) * 12 + t4 + 4];
                        af[mi][3] = Asb[(mb + g + 8) * 12 + t4 + 4];
                    }
                    #pragma unroll
                    for (int nt = 0; nt < 8; nt++) {
                        int nb = nh * 64 + nt * 8;
                        uint32_t b0 = Bsb[(nb + g) * 12 + t4];
                        uint32_t b1 = Bsb[(nb + g) * 12 + t4 + 4];
                        MMA_BF16(acc[0][nt], af[0][0], af[0][1], af[0][2], af[0][3], b0, b1);
                        MMA_BF16(acc[1][nt], af[1][0], af[1][1], af[1][2], af[1][3], b0, b1);
                    }
                }
                __syncthreads();
            }

            // epilogue: MtB[sample][kp][m] = bf16x2(M[n0], M[n0+1]) (kp = n/2)
            {
                int smp = mp >> 1;
                uint32_t* Mbase = MtB + smp * 9216;
                #pragma unroll
                for (int mi = 0; mi < 2; mi++) {
                    int mloc = (mp & 1) * 32 + mi * 16 + g;
                    #pragma unroll
                    for (int nt = 0; nt < 8; nt++) {
                        int kp = ktile * 64 + nh * 32 + nt * 4 + t4;
                        Mbase[kp * 72 + mloc]     = pack_bf16x2(acc[mi][nt][0], acc[mi][nt][1]);
                        Mbase[kp * 72 + mloc + 8] = pack_bf16x2(acc[mi][nt][2], acc[mi][nt][3]);
                    }
                }
            }
            __syncthreads();
        }

        // ---- H2 (bf16 TENSOR, k16): Hs2[s5] += sum_k e_k M[k][32+i] M[k][j] ----
        // MtB holds full 256 k as 128 kp rows; no staging, no barriers.
        {
            float hacc[2][2][4];
            #pragma unroll
            for (int a = 0; a < 2; a++)
                #pragma unroll
                for (int c = 0; c < 2; c++)
                    #pragma unroll
                    for (int d = 0; d < 4; d++) hacc[a][c][d] = 0.f;

            const float* eesN = vE + s5 * 256;
            const uint32_t* Ms = MtB + s5 * 9216;
            #pragma unroll 2
            for (int kpb = 0; kpb < 128; kpb += 8) {
                int kp0 = kpb + t4, kp1 = kpb + t4 + 4;
                uint32_t w0 = pack_bf16x2(eesN[2 * kp0], eesN[2 * kp0 + 1]);
                uint32_t w1 = pack_bf16x2(eesN[2 * kp1], eesN[2 * kp1 + 1]);
                const uint32_t* r0 = Ms + kp0 * 72;
                const uint32_t* r1 = Ms + kp1 * 72;
                uint32_t af[2][4];
                #pragma unroll
                for (int mi = 0; mi < 2; mi++) {
                    int mH = mi * 16;
                    af[mi][0] = hmul2_bf16(r0[32 + mH + g], w0);
                    af[mi][1] = hmul2_bf16(r0[32 + mH + g + 8], w0);
                    af[mi][2] = hmul2_bf16(r1[32 + mH + g], w1);
                    af[mi][3] = hmul2_bf16(r1[32 + mH + g + 8], w1);
                }
                #pragma unroll
                for (int nt = 0; nt < 2; nt++) {
                    int nb = nH + nt * 8;
                    uint32_t b0 = r0[nb + g];
                    uint32_t b1 = r1[nb + g];
                    MMA_BF16(hacc[0][nt], af[0][0], af[0][1], af[0][2], af[0][3], b0, b1);
                    MMA_BF16(hacc[1][nt], af[1][0], af[1][1], af[1][2], af[1][3], b0, b1);
                }
            }
            float* HsS = Hs2 + s5 * 2080;
            #pragma unroll
            for (int mi = 0; mi < 2; mi++)
                #pragma unroll
                for (int nt = 0; nt < 2; nt++) {
                    int j0 = nH + nt * 8 + t4 * 2;
                    int row = mi * 16 + g;
                    HsS[row * 65 + j0]           += hacc[mi][nt][0];
                    HsS[row * 65 + j0 + 1]       += hacc[mi][nt][1];
                    HsS[(row + 8) * 65 + j0]     += hacc[mi][nt][2];
                    HsS[(row + 8) * 65 + j0 + 1] += hacc[mi][nt][3];
                }
        }

        // ---- H1 (TENSOR, tf32): Hs2[s] += sum_k d_k W1T[k][32+i] W1T[k][j] ----
        {
            float* H1t = Tile5;
            const float4* W1Tv = (const float4*)W1T;
            float hacc[2][2][4];
            #pragma unroll
            for (int a = 0; a < 2; a++)
                #pragma unroll
                for (int c = 0; c < 2; c++)
                    #pragma unroll
                    for (int d = 0; d < 4; d++) hacc[a][c][d] = 0.f;

            const float* ddsN = vD + s5 * 256;
            #pragma unroll 1
            for (int kt = 0; kt < 256; kt += 16) {
                __syncthreads();   // prior tile consumed (or stage-5 tiles dead)
                {
                    int kl = tid >> 4, m4 = tid & 15;
                    *(float4*)(H1t + kl * 136 + m4 * 4) = W1Tv[(kt + kl) * 16 + m4];
                }
                __syncthreads();
                #pragma unroll
                for (int s = 0; s < 2; s++) {
                    int kb = s * 8;
                    const float* r0 = H1t + (kb + t4) * 136;
                    const float* r1 = H1t + (kb + t4 + 4) * 136;
                    float w0 = ddsN[kt + kb + t4];
                    float w1 = ddsN[kt + kb + t4 + 4];
                    uint32_t af[2][4];
                    #pragma unroll
                    for (int mi = 0; mi < 2; mi++) {
                        int mH = mi * 16;
                        af[mi][0] = to_tf32(r0[32 + mH + g] * w0);
                        af[mi][1] = to_tf32(r0[32 + mH + g + 8] * w0);
                        af[mi][2] = to_tf32(r1[32 + mH + g] * w1);
                        af[mi][3] = to_tf32(r1[32 + mH + g + 8] * w1);
                    }
                    #pragma unroll
                    for (int nt = 0; nt < 2; nt++) {
                        int nb = nH + nt * 8;
                        uint32_t b0 = to_tf32(r0[nb + g]);
                        uint32_t b1 = to_tf32(r1[nb + g]);
                        MMA_TF32(hacc[0][nt], af[0][0], af[0][1], af[0][2], af[0][3], b0, b1);
                        MMA_TF32(hacc[1][nt], af[1][0], af[1][1], af[1][2], af[1][3], b0, b1);
                    }
                }
            }
            float* HsS = Hs2 + s5 * 2080;
            #pragma unroll
            for (int mi = 0; mi < 2; mi++)
                #pragma unroll
                for (int nt = 0; nt < 2; nt++) {
                    int j0 = nH + nt * 8 + t4 * 2;
                    int row = mi * 16 + g;
                    HsS[row * 65 + j0]           += hacc[mi][nt][0];
                    HsS[row * 65 + j0 + 1]       += hacc[mi][nt][1];
                    HsS[(row + 8) * 65 + j0]     += hacc[mi][nt][2];
                    HsS[(row + 8) * 65 + j0 + 1] += hacc[mi][nt][3];
                }
        }
        __syncthreads();
    }

    // ---- Solve (2 warps, one per sample) ----
    float* Sv = MtBf;   // dead
    if (tid < 64) {
        int ws = tid >> 5, ln = tid & 31;
        const float* HsS = Hs2 + ws * 2080;
        float* SvN = Sv + ws * 1088;
        const float* qd = xs + ws * 64 + 32;
        float r = HsS[ln * 65 + 64];   // gsA
        #pragma unroll 8
        for (int j = 0; j < 32; j++) r -= HsS[ln * 65 + j] * qd[j];
        #pragma unroll 8
        for (int j = 0; j < 32; j++)
            SvN[ln * 34 + j] = HsS[ln * 65 + 32 + j] + ((ln == j) ? 2.0f : 0.0f);
        SvN[ln * 34 + 32] = r;
        __syncwarp();

        for (int p = 0; p < 32; p++) {
            float v = (ln >= p) ? fabsf(SvN[ln * 34 + p]) : -1.0f;
            int idx = ln;
            #pragma unroll
            for (int off = 16; off; off >>= 1) {
                float v2 = __shfl_xor_sync(0xffffffffu, v, off);
                int   i2 = __shfl_xor_sync(0xffffffffu, idx, off);
                if (v2 > v || (v2 == v && i2 < idx)) { v = v2; idx = i2; }
            }
            if (idx != p) {
                float t1 = SvN[p * 34 + ln];
                SvN[p * 34 + ln]   = SvN[idx * 34 + ln];
                SvN[idx * 34 + ln] = t1;
                if (ln == 0) {
                    float t2 = SvN[p * 34 + 32];
                    SvN[p * 34 + 32]   = SvN[idx * 34 + 32];
                    SvN[idx * 34 + 32] = t2;
                }
            }
            __syncwarp();
            float pinvv = 1.0f / SvN[p * 34 + p];
            if (ln != p) {
                float f = SvN[ln * 34 + p] * pinvv;
                for (int c = p; c < 33; c++)
                    SvN[ln * 34 + c] -= f * SvN[p * 34 + c];
            }
            __syncwarp();
        }
        float qdd = SvN[ln * 34 + 32] / SvN[ln * 34 + ln];
        int sample = b * 2 + ws;
        out[sample * 64 + ln]      = xs[ws * 64 + 32 + ln];
        out[sample * 64 + 32 + ln] = qdd;
    }
}

extern "C" void kernel_launch(void* const* d_in, const int* in_sizes, int n_in,
                              void* d_out, int out_size)
{
    const float* x   = (const float*)d_in[0];
    const float* W1m = (const float*)d_in[1];
    const float* b1m = (const float*)d_in[2];
    const float* W2m = (const float*)d_in[3];
    const float* b2m = (const float*)d_in[4];
    const float* W3m = (const float*)d_in[5];
    const float* W1q = (const float*)d_in[6];
    const float* b1q = (const float*)d_in[7];
    const float* W2q = (const float*)d_in[8];
    const float* b2q = (const float*)d_in[9];
    const float* W3q = (const float*)d_in[10];
    float* out = (float*)d_out;

    int B = in_sizes[0] / 64;

    prep_kernel<<<256, 256>>>(W1m, W2m, W1q, W2q);
    cudaFuncSetAttribute(lnn_kernel, cudaFuncAttributeMaxDynamicSharedMemorySize, SMEM_BYTES);
    lnn_kernel<<<B / 2, 256, SMEM_BYTES>>>(x, W1m, b1m, W2m, b2m, W3m,
                                           W1q, b1q, W2q, b2q, W3q, out);
}

// round 16
// speedup vs baseline: 1.5403x; 1.1019x over previous
#include <cuda_runtime.h>
#include <math.h>
#include <stdint.h>

#define HD 256
#define DD 64

__device__ float g_W1T[2 * DD * HD];       // [pass][(j*64 + m)]
__device__ float g_W2T[2 * HD * HD];       // [pass][(k*256 + j)]
__device__ uint32_t g_W1Tb[2 * 128 * 64];  // [pass][jp][m] bf16x2(W1T[2jp][m],W1T[2jp+1][m])
__device__ uint32_t g_W2b[2 * 128 * 256];  // [pass][jp][n] bf16x2(W2[2jp][n],W2[2jp+1][n])

__device__ __forceinline__ uint32_t pack_bf16x2(float lo, float hi) {
    uint32_t r;
    asm("cvt.rn.bf16x2.f32 %0, %1, %2;" : "=r"(r) : "f"(hi), "f"(lo));
    return r;
}

__global__ void prep_kernel(const float* __restrict__ W1m, const float* __restrict__ W2m,
                            const float* __restrict__ W1q, const float* __restrict__ W2q)
{
    int t = blockIdx.x * blockDim.x + threadIdx.x;
    if (t < DD * HD) {
        int j = t >> 6, m = t & 63;
        g_W1T[t]           = W1m[m * HD + j];
        g_W1T[DD * HD + t] = W1q[m * HD + j];
    }
    if (t < HD * HD) {
        int k = t >> 8, j = t & 255;
        g_W2T[t]           = W2m[j * HD + k];
        g_W2T[HD * HD + t] = W2q[j * HD + k];
    }
    if (t < 128 * 64) {
        int jp = t >> 6, m = t & 63;
        g_W1Tb[t]            = pack_bf16x2(W1m[m * HD + 2 * jp], W1m[m * HD + 2 * jp + 1]);
        g_W1Tb[128 * 64 + t] = pack_bf16x2(W1q[m * HD + 2 * jp], W1q[m * HD + 2 * jp + 1]);
    }
    if (t < 128 * 256) {
        int jp = t >> 8, n = t & 255;
        g_W2b[t]             = pack_bf16x2(W2m[(2 * jp) * HD + n], W2m[(2 * jp + 1) * HD + n]);
        g_W2b[128 * 256 + t] = pack_bf16x2(W2q[(2 * jp) * HD + n], W2q[(2 * jp + 1) * HD + n]);
    }
}

__device__ __forceinline__ uint32_t hmul2_bf16(uint32_t a, uint32_t b) {
    uint32_t r;
    asm("mul.rn.bf16x2 %0, %1, %2;" : "=r"(r) : "r"(a), "r"(b));
    return r;
}

#define MMA_BF16(acc, a0, a1, a2, a3, b0, b1)                                   \
    asm volatile(                                                               \
        "mma.sync.aligned.m16n8k16.row.col.f32.bf16.bf16.f32 "                  \
        "{%0,%1,%2,%3}, {%4,%5,%6,%7}, {%8,%9}, {%0,%1,%2,%3};\n"               \
        : "+f"(acc[0]), "+f"(acc[1]), "+f"(acc[2]), "+f"(acc[3])                \
        : "r"(a0), "r"(a1), "r"(a2), "r"(a3), "r"(b0), "r"(b1))

// Shared memory (floats), NS=2 samples per CTA:
//   MtB   [2][128][72] 18432  M packed bf16x2 (kp = n/2), pitch 72; Sv in solve
//   Tile5 3072: Asb 128x12 uint bf16x2 A-tile, Bsb 128x12 uint B-tile
//   Hs2   [2][32][65]  4160   H rows 32..63/sample; col 64 = gsA (rows 0..31)
//   vA/vB/vC/vD/vE 512 each (vA/vB reused as packed uCp/uDp/uEp)
//   xs 128
#define SMEM_FLOATS (18432 + 3072 + 4160 + 5*512 + 128)
#define SMEM_BYTES  (SMEM_FLOATS * 4)

__global__ __launch_bounds__(256, 2)
void lnn_kernel(const float* __restrict__ x,
                const float* __restrict__ W1m, const float* __restrict__ b1m,
                const float* __restrict__ W2m, const float* __restrict__ b2m,
                const float* __restrict__ W3m,
                const float* __restrict__ W1q, const float* __restrict__ b1q,
                const float* __restrict__ W2q, const float* __restrict__ b2q,
                const float* __restrict__ W3q,
                float* __restrict__ out)
{
    extern __shared__ float sm[];
    float* MtBf  = sm;                // 18432
    float* Tile5 = MtBf + 18432;      // 3072
    float* Hs2   = Tile5 + 3072;      // 4160
    float* vA    = Hs2 + 4160;        // 512
    float* vB    = vA + 512;          // 512
    float* vC    = vB + 512;          // 512
    float* vD    = vC + 512;          // 512
    float* vE    = vD + 512;          // 512
    float* xs    = vE + 512;          // 128

    uint32_t* MtB = (uint32_t*)MtBf;          // [2][128 kp][72]
    uint32_t* Asb = (uint32_t*)Tile5;         // 1536 uint (128 x 12)
    uint32_t* Bsb = (uint32_t*)(Tile5 + 1536);// 1536 uint (128 x 12)
    uint32_t* uCp = (uint32_t*)vA;            // [ns*128+jp] packed aas pairs
    uint32_t* uDp = uCp + 256;                // packed dds pairs
    uint32_t* uEp = (uint32_t*)vB;            // packed ees pairs

    const int tid = threadIdx.x;
    const int b   = blockIdx.x;      // samples 2b, 2b+1

    for (int q = tid; q < 4160; q += 256) Hs2[q] = 0.0f;
    if (tid < 128) xs[tid] = x[b * 128 + tid];
    __syncthreads();

    const int wid = tid >> 5, lane = tid & 31;
    const int g = lane >> 2, t4 = lane & 3;

    #pragma unroll 1
    for (int pass = 0; pass < 2; pass++) {
        const float* W1  = pass ? W1q : W1m;
        const float* b1  = pass ? b1q : b1m;
        const float* W2  = pass ? W2q : W2m;
        const float* b2  = pass ? b2q : b2m;
        const float* W3  = pass ? W3q : W3m;
        const float* W1T = g_W1T + pass * (DD * HD);
        const float* W2T = g_W2T + pass * (HD * HD);
        const uint32_t* W1Tb = g_W1Tb + pass * (128 * 64);
        const uint32_t* W2b  = g_W2b + pass * (128 * 256);

        // ---- Stage 1: z1 = x W1 + b1 (both samples); h1, a, s ----
        {
            int j = tid;
            float bv = b1[j];
            float p0 = bv, p1 = 0.f, p2 = 0.f, p3 = 0.f;
            float q0 = bv, q1 = 0.f, q2 = 0.f, q3 = 0.f;
            const float4* x0 = (const float4*)xs;
            const float4* x1 = (const float4*)(xs + 64);
            #pragma unroll 4
            for (int i4 = 0; i4 < 16; i4++) {
                int i = i4 * 4;
                float w0 = W1[(i + 0) * HD + j];
                float w1 = W1[(i + 1) * HD + j];
                float w2 = W1[(i + 2) * HD + j];
                float w3 = W1[(i + 3) * HD + j];
                float4 u0 = x0[i4], u1 = x1[i4];
                p0 = fmaf(u0.x, w0, p0); q0 = fmaf(u1.x, w0, q0);
                p1 = fmaf(u0.y, w1, p1); q1 = fmaf(u1.y, w1, q1);
                p2 = fmaf(u0.z, w2, p2); q2 = fmaf(u1.z, w2, q2);
                p3 = fmaf(u0.w, w3, p3); q3 = fmaf(u1.w, w3, q3);
            }
            float z0v = (p0 + p1) + (p2 + p3);
            float z1v = (q0 + q1) + (q2 + q3);
            #pragma unroll
            for (int ns = 0; ns < 2; ns++) {
                float z = ns ? z1v : z0v;
                float h, a, s;
                if (pass == 0) {
                    float sg = 1.0f / (1.0f + __expf(-z));
                    h = fmaxf(z, 0.0f) + log1pf(__expf(-fabsf(z)));
                    a = sg;
                    s = sg * (1.0f - sg);
                } else {
                    float t = tanhf(0.5f * z);
                    float o = 1.0f - t * t;
                    h = z * t;
                    a = fmaf(0.5f * z, o, t);
                    s = o * (1.0f - 0.5f * z * t);
                }
                vA[ns * 256 + j] = h;
                vC[ns * 256 + j] = a;
                vD[ns * 256 + j] = s;
            }
        }
        __syncthreads();

        // ---- Stage 2: z2 = h1 W2 + b2 ; c, e ----
        {
            int k = tid;
            float bv = b2[k];
            float p0 = bv, p1 = 0.f, p2 = 0.f, p3 = 0.f;
            float q0 = bv, q1 = 0.f, q2 = 0.f, q3 = 0.f;
            const float4* h0 = (const float4*)vA;
            const float4* h1v = (const float4*)(vA + 256);
            #pragma unroll 4
            for (int l4 = 0; l4 < 64; l4++) {
                int l = l4 * 4;
                float w0 = W2[(l + 0) * HD + k];
                float w1 = W2[(l + 1) * HD + k];
                float w2 = W2[(l + 2) * HD + k];
                float w3 = W2[(l + 3) * HD + k];
                float4 u0 = h0[l4], u1 = h1v[l4];
                p0 = fmaf(u0.x, w0, p0); q0 = fmaf(u1.x, w0, q0);
                p1 = fmaf(u0.y, w1, p1); q1 = fmaf(u1.y, w1, q1);
                p2 = fmaf(u0.z, w2, p2); q2 = fmaf(u1.z, w2, q2);
                p3 = fmaf(u0.w, w3, p3); q3 = fmaf(u1.w, w3, q3);
            }
            float z0v = (p0 + p1) + (p2 + p3);
            float z1v = (q0 + q1) + (q2 + q3);
            float w3v = W3[k];
            #pragma unroll
            for (int ns = 0; ns < 2; ns++) {
                float z = ns ? z1v : z0v;
                float a, s;
                if (pass == 0) {
                    float sg = 1.0f / (1.0f + __expf(-z));
                    a = sg;
                    s = sg * (1.0f - sg);
                } else {
                    float t = tanhf(0.5f * z);
                    float o = 1.0f - t * t;
                    a = fmaf(0.5f * z, o, t);
                    s = o * (1.0f - 0.5f * z * t);
                }
                vB[ns * 256 + k] = a * w3v;
                vE[ns * 256 + k] = s * w3v;
            }
        }
        __syncthreads();

        // ---- Stage 3: u = W2 c ; dds = s*u, aus = a*u ----
        {
            int j = tid;
            float p0 = 0.f, p1 = 0.f, p2 = 0.f, p3 = 0.f;
            float q0 = 0.f, q1 = 0.f, q2 = 0.f, q3 = 0.f;
            const float4* c0 = (const float4*)vB;
            const float4* c1 = (const float4*)(vB + 256);
            #pragma unroll 4
            for (int k4 = 0; k4 < 64; k4++) {
                int k = k4 * 4;
                float w0 = W2T[(k + 0) * HD + j];
                float w1 = W2T[(k + 1) * HD + j];
                float w2 = W2T[(k + 2) * HD + j];
                float w3 = W2T[(k + 3) * HD + j];
                float4 u0 = c0[k4], u1 = c1[k4];
                p0 = fmaf(u0.x, w0, p0); q0 = fmaf(u1.x, w0, q0);
                p1 = fmaf(u0.y, w1, p1); q1 = fmaf(u1.y, w1, q1);
                p2 = fmaf(u0.z, w2, p2); q2 = fmaf(u1.z, w2, q2);
                p3 = fmaf(u0.w, w3, p3); q3 = fmaf(u1.w, w3, q3);
            }
            float u0v = (p0 + p1) + (p2 + p3);
            float u1v = (q0 + q1) + (q2 + q3);
            float s0 = vD[j], s1 = vD[256 + j];
            float a0 = vC[j], a1 = vC[256 + j];
            vD[j]       = s0 * u0v;  vD[256 + j] = s1 * u1v;
            vA[j]       = a0 * u0v;  vA[256 + j] = a1 * u1v;
        }
        __syncthreads();

        // ---- Stage 4: g = W1 (a*u), 4-way j-split, both samples ----
        {
            int m = tid & 63, part = tid >> 6;
            const float* W1Tp = W1T + part * 64 * 64;
            const float4* a0 = (const float4*)(vA + part * 64);
            const float4* a1 = (const float4*)(vA + 256 + part * 64);
            float p0 = 0.f, p1 = 0.f, p2 = 0.f, p3 = 0.f;
            float q0 = 0.f, q1 = 0.f, q2 = 0.f, q3 = 0.f;
            #pragma unroll 4
            for (int j4 = 0; j4 < 16; j4++) {
                int jj = j4 * 4;
                float w0 = W1Tp[(jj + 0) * 64 + m];
                float w1 = W1Tp[(jj + 1) * 64 + m];
                float w2 = W1Tp[(jj + 2) * 64 + m];
                float w3 = W1Tp[(jj + 3) * 64 + m];
                float4 u0 = a0[j4], u1 = a1[j4];
                p0 = fmaf(w0, u0.x, p0); q0 = fmaf(w0, u1.x, q0);
                p1 = fmaf(w1, u0.y, p1); q1 = fmaf(w1, u1.y, q1);
                p2 = fmaf(w2, u0.z, p2); q2 = fmaf(w2, u1.z, q2);
                p3 = fmaf(w3, u0.w, p3); q3 = fmaf(w3, u1.w, q3);
            }
            float g0 = (p0 + p1) + (p2 + p3);
            float g1 = (q0 + q1) + (q2 + q3);
            vB[part * 64 + m]       = g0;   // ccs dead after stage 3 sync
            vB[256 + part * 64 + m] = g1;
        }
        __syncthreads();
        // g[0..31] only; Hs2 has 32 rows per sample.
        if (tid < 64) {
            int ns = tid >> 5, mm = tid & 31;
            const float* gp = vB + ns * 256;
            Hs2[ns * 2080 + mm * 65 + 64] += gp[mm] + gp[64 + mm] + gp[128 + mm] + gp[192 + mm];
        }
        __syncthreads();   // vB (gpart) consumed before uEp overwrite

        // ---- pack scale pairs: uCp (aas), uDp (dds), uEp (ees) ----
        {
            int ns = tid >> 7, jp = tid & 127;
            uCp[tid] = pack_bf16x2(vC[ns * 256 + 2 * jp], vC[ns * 256 + 2 * jp + 1]);
            uDp[tid] = pack_bf16x2(vD[ns * 256 + 2 * jp], vD[ns * 256 + 2 * jp + 1]);
            uEp[tid] = pack_bf16x2(vE[ns * 256 + 2 * jp], vE[ns * 256 + 2 * jp + 1]);
        }
        __syncthreads();

        // ---- Stage 5 (bf16 TENSOR) per n-chunk of 128; M stored packed bf16x2 ----
        const int mp  = wid & 3;           // m rows mp*32 .. +31 (m' = 2x64)
        const int nh  = wid >> 2;          // n cols nh*64 .. +63
        const int s5  = wid & 1;           // H-phase sample
        const int nH  = (wid >> 1) * 16;   // H-phase col group
        const int mq   = tid & 127;
        const int half = tid >> 7;
        const int smp5 = mq >> 6, ml5 = mq & 63;

        #pragma unroll 1
        for (int ktile = 0; ktile < 2; ktile++) {
            float acc[2][8][4];
            #pragma unroll
            for (int mi = 0; mi < 2; mi++)
                #pragma unroll
                for (int i = 0; i < 8; i++)
                    #pragma unroll
                    for (int j = 0; j < 4; j++) acc[mi][i][j] = 0.f;

            #pragma unroll 1
            for (int jt = 0; jt < 256; jt += 16) {
                int jp0 = (jt >> 1) + half * 4;
                // stage A: Asb[m'][jp] = W1Tb[jp][m] *bf16 aas-pair
                {
                    uint32_t pk[4];
                    #pragma unroll
                    for (int p = 0; p < 4; p++)
                        pk[p] = hmul2_bf16(W1Tb[(jp0 + p) * 64 + ml5],
                                           uCp[smp5 * 128 + jp0 + p]);
                    *(uint4*)(Asb + mq * 12 + half * 4) = make_uint4(pk[0], pk[1], pk[2], pk[3]);
                }
                // stage B: Bsb[n][jp] = W2b[jp][ktile*128 + n]
                {
                    uint32_t pk[4];
                    #pragma unroll
                    for (int p = 0; p < 4; p++)
                        pk[p] = W2b[(jp0 + p) * 256 + ktile * 128 + mq];
                    *(uint4*)(Bsb + mq * 12 + half * 4) = make_uint4(pk[0], pk[1], pk[2], pk[3]);
                }
                __syncthreads();

                {
                    uint32_t af[2][4];
                    #pragma unroll
                    for (int mi = 0; mi < 2; mi++) {
                        int mb = mp * 32 + mi * 16;
                        af[mi][0] = Asb[(mb + g) * 12 + t4];
                        af[mi][1] = Asb[(mb + g + 8) * 12 + t4];
                        af[mi][2] = Asb[(mb + g) * 12 + t4 + 4];
                        af[mi][3] = Asb[(mb + g + 8) * 12 + t4 + 4];
                    }
                    #pragma unroll
                    for (int nt = 0; nt < 8; nt++) {
                        int nb = nh * 64 + nt * 8;
                        uint32_t b0 = Bsb[(nb + g) * 12 + t4];
                        uint32_t b1 = Bsb[(nb + g) * 12 + t4 + 4];
                        MMA_BF16(acc[0][nt], af[0][0], af[0][1], af[0][2], af[0][3], b0, b1);
                        MMA_BF16(acc[1][nt], af[1][0], af[1][1], af[1][2], af[1][3], b0, b1);
                    }
                }
                __syncthreads();
            }

            // epilogue: MtB[sample][kp][m] = bf16x2(M[n0], M[n0+1])
            {
                int smp = mp >> 1;
                uint32_t* Mbase = MtB + smp * 9216;
                #pragma unroll
                for (int mi = 0; mi < 2; mi++) {
                    int mloc = (mp & 1) * 32 + mi * 16 + g;
                    #pragma unroll
                    for (int nt = 0; nt < 8; nt++) {
                        int kp = ktile * 64 + nh * 32 + nt * 4 + t4;
                        Mbase[kp * 72 + mloc]     = pack_bf16x2(acc[mi][nt][0], acc[mi][nt][1]);
                        Mbase[kp * 72 + mloc + 8] = pack_bf16x2(acc[mi][nt][2], acc[mi][nt][3]);
                    }
                }
            }
            __syncthreads();
        }

        // ---- H2 (bf16, k16): Hs2[s5] += sum_k e_k M[k][32+i] M[k][j] ----
        {
            float hacc[2][2][4];
            #pragma unroll
            for (int a = 0; a < 2; a++)
                #pragma unroll
                for (int c = 0; c < 2; c++)
                    #pragma unroll
                    for (int d = 0; d < 4; d++) hacc[a][c][d] = 0.f;

            const uint32_t* Ms = MtB + s5 * 9216;
            const uint32_t* eP = uEp + s5 * 128;
            #pragma unroll 2
            for (int kpb = 0; kpb < 128; kpb += 8) {
                int kp0 = kpb + t4, kp1 = kpb + t4 + 4;
                uint32_t w0 = eP[kp0], w1 = eP[kp1];
                const uint32_t* r0 = Ms + kp0 * 72;
                const uint32_t* r1 = Ms + kp1 * 72;
                uint32_t af[2][4];
                #pragma unroll
                for (int mi = 0; mi < 2; mi++) {
                    int mH = mi * 16;
                    af[mi][0] = hmul2_bf16(r0[32 + mH + g], w0);
                    af[mi][1] = hmul2_bf16(r0[32 + mH + g + 8], w0);
                    af[mi][2] = hmul2_bf16(r1[32 + mH + g], w1);
                    af[mi][3] = hmul2_bf16(r1[32 + mH + g + 8], w1);
                }
                #pragma unroll
                for (int nt = 0; nt < 2; nt++) {
                    int nb = nH + nt * 8;
                    uint32_t b0 = r0[nb + g];
                    uint32_t b1 = r1[nb + g];
                    MMA_BF16(hacc[0][nt], af[0][0], af[0][1], af[0][2], af[0][3], b0, b1);
                    MMA_BF16(hacc[1][nt], af[1][0], af[1][1], af[1][2], af[1][3], b0, b1);
                }
            }

            // ---- H1 (bf16, k16, barrier-free): += sum_k d_k W1T[k][32+i] W1T[k][j]
            const uint32_t* dP = uDp + s5 * 128;
            #pragma unroll 2
            for (int kpb = 0; kpb < 128; kpb += 8) {
                int kp0 = kpb + t4, kp1 = kpb + t4 + 4;
                uint32_t w0 = dP[kp0], w1 = dP[kp1];
                const uint32_t* r0 = W1Tb + kp0 * 64;
                const uint32_t* r1 = W1Tb + kp1 * 64;
                uint32_t af[2][4];
                #pragma unroll
                for (int mi = 0; mi < 2; mi++) {
                    int mH = mi * 16;
                    af[mi][0] = hmul2_bf16(r0[32 + mH + g], w0);
                    af[mi][1] = hmul2_bf16(r0[32 + mH + g + 8], w0);
                    af[mi][2] = hmul2_bf16(r1[32 + mH + g], w1);
                    af[mi][3] = hmul2_bf16(r1[32 + mH + g + 8], w1);
                }
                #pragma unroll
                for (int nt = 0; nt < 2; nt++) {
                    int nb = nH + nt * 8;
                    uint32_t b0 = r0[nb + g];
                    uint32_t b1 = r1[nb + g];
                    MMA_BF16(hacc[0][nt], af[0][0], af[0][1], af[0][2], af[0][3], b0, b1);
                    MMA_BF16(hacc[1][nt], af[1][0], af[1][1], af[1][2], af[1][3], b0, b1);
                }
            }

            float* HsS = Hs2 + s5 * 2080;
            #pragma unroll
            for (int mi = 0; mi < 2; mi++)
                #pragma unroll
                for (int nt = 0; nt < 2; nt++) {
                    int j0 = nH + nt * 8 + t4 * 2;
                    int row = mi * 16 + g;
                    HsS[row * 65 + j0]           += hacc[mi][nt][0];
                    HsS[row * 65 + j0 + 1]       += hacc[mi][nt][1];
                    HsS[(row + 8) * 65 + j0]     += hacc[mi][nt][2];
                    HsS[(row + 8) * 65 + j0 + 1] += hacc[mi][nt][3];
                }
        }
        __syncthreads();
    }

    // ---- Solve (2 warps, one per sample) ----
    float* Sv = MtBf;   // dead
    if (tid < 64) {
        int ws = tid >> 5, ln = tid & 31;
        const float* HsS = Hs2 + ws * 2080;
        float* SvN = Sv + ws * 1088;
        const float* qd = xs + ws * 64 + 32;
        float r = HsS[ln * 65 + 64];   // gsA
        #pragma unroll 8
        for (int j = 0; j < 32; j++) r -= HsS[ln * 65 + j] * qd[j];
        #pragma unroll 8
        for (int j = 0; j < 32; j++)
            SvN[ln * 34 + j] = HsS[ln * 65 + 32 + j] + ((ln == j) ? 2.0f : 0.0f);
        SvN[ln * 34 + 32] = r;
        __syncwarp();

        for (int p = 0; p < 32; p++) {
            float v = (ln >= p) ? fabsf(SvN[ln * 34 + p]) : -1.0f;
            int idx = ln;
            #pragma unroll
            for (int off = 16; off; off >>= 1) {
                float v2 = __shfl_xor_sync(0xffffffffu, v, off);
                int   i2 = __shfl_xor_sync(0xffffffffu, idx, off);
                if (v2 > v || (v2 == v && i2 < idx)) { v = v2; idx = i2; }
            }
            if (idx != p) {
                float t1 = SvN[p * 34 + ln];
                SvN[p * 34 + ln]   = SvN[idx * 34 + ln];
                SvN[idx * 34 + ln] = t1;
                if (ln == 0) {
                    float t2 = SvN[p * 34 + 32];
                    SvN[p * 34 + 32]   = SvN[idx * 34 + 32];
                    SvN[idx * 34 + 32] = t2;
                }
            }
            __syncwarp();
            float pinvv = 1.0f / SvN[p * 34 + p];
            if (ln != p) {
                float f = SvN[ln * 34 + p] * pinvv;
                for (int c = p; c < 33; c++)
                    SvN[ln * 34 + c] -= f * SvN[p * 34 + c];
            }
            __syncwarp();
        }
        float qdd = SvN[ln * 34 + 32] / SvN[ln * 34 + ln];
        int sample = b * 2 + ws;
        out[sample * 64 + ln]      = xs[ws * 64 + 32 + ln];
        out[sample * 64 + 32 + ln] = qdd;
    }
}

extern "C" void kernel_launch(void* const* d_in, const int* in_sizes, int n_in,
                              void* d_out, int out_size)
{
    const float* x   = (const float*)d_in[0];
    const float* W1m = (const float*)d_in[1];
    const float* b1m = (const float*)d_in[2];
    const float* W2m = (const float*)d_in[3];
    const float* b2m = (const float*)d_in[4];
    const float* W3m = (const float*)d_in[5];
    const float* W1q = (const float*)d_in[6];
    const float* b1q = (const float*)d_in[7];
    const float* W2q = (const float*)d_in[8];
    const float* b2q = (const float*)d_in[9];
    const float* W3q = (const float*)d_in[10];
    float* out = (float*)d_out;

    int B = in_sizes[0] / 64;

    prep_kernel<<<256, 256>>>(W1m, W2m, W1q, W2q);
    cudaFuncSetAttribute(lnn_kernel, cudaFuncAttributeMaxDynamicSharedMemorySize, SMEM_BYTES);
    lnn_kernel<<<B / 2, 256, SMEM_BYTES>>>(x, W1m, b1m, W2m, b2m, W3m,
                                           W1q, b1q, W2q, b2q, W3q, out);
}

// round 17
// speedup vs baseline: 2.0162x; 1.3089x over previous
#include <cuda_runtime.h>
#include <math.h>
#include <stdint.h>

#define HD 256
#define DD 64

__device__ float g_W1T[2 * DD * HD];       // [pass][(j*64 + m)]
__device__ float g_W2T[2 * HD * HD];       // [pass][(k*256 + j)]
// Pre-shuffled mma fragment tables (lane-order, coalesced):
__device__ uint4 g_W1Tf[2 * 16 * 2 * 2 * 32];      // [pass][jt4][mp2][mi][lane] stage-5 A
__device__ uint2 g_W2f[2 * 2 * 16 * 2 * 8 * 32];   // [pass][ktile][jt4][nh][nt][lane] stage-5 B
__device__ uint4 g_W1Ha[2 * 16 * 2 * 32];          // [pass][kpb4][mi][lane] H1 A-source
__device__ uint2 g_W1Hb[2 * 16 * 4 * 2 * 32];      // [pass][kpb4][nH4][nt][lane] H1 B

__device__ __forceinline__ uint32_t pack_bf16x2(float lo, float hi) {
    uint32_t r;
    asm("cvt.rn.bf16x2.f32 %0, %1, %2;" : "=r"(r) : "f"(hi), "f"(lo));
    return r;
}

// W1 layout [64 m][256 j]: pack hidden pair (2jp, 2jp+1) at row m
__device__ __forceinline__ uint32_t PW1(const float* W1p, int m, int jp) {
    return pack_bf16x2(W1p[m * HD + 2 * jp], W1p[m * HD + 2 * jp + 1]);
}
// W2 layout [256 j][256 n]: pack hidden pair at column n
__device__ __forceinline__ uint32_t PW2(const float* W2p, int jp, int n) {
    return pack_bf16x2(W2p[(2 * jp) * HD + n], W2p[(2 * jp + 1) * HD + n]);
}

__global__ void prep_kernel(const float* __restrict__ W1m, const float* __restrict__ W2m,
                            const float* __restrict__ W1q, const float* __restrict__ W2q)
{
    int t = blockIdx.x * blockDim.x + threadIdx.x;
    if (t < DD * HD) {
        int j = t >> 6, m = t & 63;
        g_W1T[t]           = W1m[m * HD + j];
        g_W1T[DD * HD + t] = W1q[m * HD + j];
    }
    if (t < HD * HD) {
        int k = t >> 8, j = t & 255;
        g_W2T[t]           = W2m[j * HD + k];
        g_W2T[HD * HD + t] = W2q[j * HD + k];
    }
    const float* W1p[2] = {W1m, W1q};
    const float* W2p[2] = {W2m, W2q};
    if (t < 2048) {       // W1Tf: lane|mi<<5|mp2<<6|jt4<<7
        int lane = t & 31, mi = (t >> 5) & 1, mp2 = (t >> 6) & 1, jt4 = t >> 7;
        int g = lane >> 2, t4 = lane & 3;
        int mb = mp2 * 32 + mi * 16, jp0 = jt4 * 8 + t4;
        #pragma unroll
        for (int p = 0; p < 2; p++) {
            uint4 v;
            v.x = PW1(W1p[p], mb + g,     jp0);
            v.y = PW1(W1p[p], mb + g + 8, jp0);
            v.z = PW1(W1p[p], mb + g,     jp0 + 4);
            v.w = PW1(W1p[p], mb + g + 8, jp0 + 4);
            g_W1Tf[p * 2048 + t] = v;
        }
    }
    if (t < 16384) {      // W2f: lane|nt<<5|nh<<8|jt4<<9|kt<<13
        int lane = t & 31, nt = (t >> 5) & 7, nh = (t >> 8) & 1;
        int jt4 = (t >> 9) & 15, kt = t >> 13;
        int g = lane >> 2, t4 = lane & 3;
        int n = kt * 128 + nh * 64 + nt * 8 + g;
        int jp0 = jt4 * 8 + t4;
        #pragma unroll
        for (int p = 0; p < 2; p++) {
            uint2 v;
            v.x = PW2(W2p[p], jp0,     n);
            v.y = PW2(W2p[p], jp0 + 4, n);
            g_W2f[p * 16384 + t] = v;
        }
    }
    if (t < 1024) {       // W1Ha: lane|mi<<5|kpb4<<6
        int lane = t & 31, mi = (t >> 5) & 1, kpb4 = t >> 6;
        int g = lane >> 2, t4 = lane & 3;
        int kp0 = kpb4 * 8 + t4;
        int mc = 32 + mi * 16 + g;
        #pragma unroll
        for (int p = 0; p < 2; p++) {
            uint4 v;
            v.x = PW1(W1p[p], mc,     kp0);
            v.y = PW1(W1p[p], mc + 8, kp0);
            v.z = PW1(W1p[p], mc,     kp0 + 4);
            v.w = PW1(W1p[p], mc + 8, kp0 + 4);
            g_W1Ha[p * 1024 + t] = v;
        }
    }
    if (t < 4096) {       // W1Hb: lane|nt<<5|nH4<<6|kpb4<<8
        int lane = t & 31, nt = (t >> 5) & 1, nH4 = (t >> 6) & 3, kpb4 = t >> 8;
        int g = lane >> 2, t4 = lane & 3;
        int n = nH4 * 16 + nt * 8 + g;
        int kp0 = kpb4 * 8 + t4;
        #pragma unroll
        for (int p = 0; p < 2; p++) {
            uint2 v;
            v.x = PW1(W1p[p], n, kp0);
            v.y = PW1(W1p[p], n, kp0 + 4);
            g_W1Hb[p * 4096 + t] = v;
        }
    }
}

__device__ __forceinline__ uint32_t hmul2_bf16(uint32_t a, uint32_t b) {
    uint32_t r;
    asm("mul.rn.bf16x2 %0, %1, %2;" : "=r"(r) : "r"(a), "r"(b));
    return r;
}

#define MMA_BF16(acc, a0, a1, a2, a3, b0, b1)                                   \
    asm volatile(                                                               \
        "mma.sync.aligned.m16n8k16.row.col.f32.bf16.bf16.f32 "                  \
        "{%0,%1,%2,%3}, {%4,%5,%6,%7}, {%8,%9}, {%0,%1,%2,%3};\n"               \
        : "+f"(acc[0]), "+f"(acc[1]), "+f"(acc[2]), "+f"(acc[3])                \
        : "r"(a0), "r"(a1), "r"(a2), "r"(a3), "r"(b0), "r"(b1))

// Shared memory (floats), NS=2 samples per CTA:
//   MtB   [2][128][72] 18432  M packed bf16x2 (kp = n/2), pitch 72; Sv in solve
//   Hs2   [2][32][65]  4160   H rows 32..63/sample; col 64 = gsA (rows 0..31)
//   vA/vB/vC/vD/vE 512 each (vA/vB reused as packed uCp/uDp/uEp)
//   xs 128
// Total 25,280 floats = 101,120 B -> 2 CTAs/SM.
#define SMEM_FLOATS (18432 + 4160 + 5*512 + 128)
#define SMEM_BYTES  (SMEM_FLOATS * 4)

__global__ __launch_bounds__(256, 2)
void lnn_kernel(const float* __restrict__ x,
                const float* __restrict__ W1m, const float* __restrict__ b1m,
                const float* __restrict__ W2m, const float* __restrict__ b2m,
                const float* __restrict__ W3m,
                const float* __restrict__ W1q, const float* __restrict__ b1q,
                const float* __restrict__ W2q, const float* __restrict__ b2q,
                const float* __restrict__ W3q,
                float* __restrict__ out)
{
    extern __shared__ float sm[];
    float* MtBf  = sm;                // 18432
    float* Hs2   = MtBf + 18432;      // 4160
    float* vA    = Hs2 + 4160;        // 512
    float* vB    = vA + 512;          // 512
    float* vC    = vB + 512;          // 512
    float* vD    = vC + 512;          // 512
    float* vE    = vD + 512;          // 512
    float* xs    = vE + 512;          // 128

    uint32_t* MtB = (uint32_t*)MtBf;  // [2][128 kp][72]
    uint32_t* uCp = (uint32_t*)vA;    // packed aas pairs [ns*128+jp]
    uint32_t* uDp = uCp + 256;        // packed dds pairs
    uint32_t* uEp = (uint32_t*)vB;    // packed ees pairs

    const int tid = threadIdx.x;
    const int b   = blockIdx.x;       // samples 2b, 2b+1

    for (int q = tid; q < 4160; q += 256) Hs2[q] = 0.0f;
    if (tid < 128) xs[tid] = x[b * 128 + tid];
    __syncthreads();

    const int wid = tid >> 5, lane = tid & 31;
    const int g = lane >> 2, t4 = lane & 3;

    #pragma unroll 1
    for (int pass = 0; pass < 2; pass++) {
        const float* W1  = pass ? W1q : W1m;
        const float* b1  = pass ? b1q : b1m;
        const float* W2  = pass ? W2q : W2m;
        const float* b2  = pass ? b2q : b2m;
        const float* W3  = pass ? W3q : W3m;
        const float* W1T = g_W1T + pass * (DD * HD);
        const float* W2T = g_W2T + pass * (HD * HD);
        const uint4* Af = g_W1Tf + pass * 2048;
        const uint2* Bf = g_W2f + pass * 16384;
        const uint4* Ha = g_W1Ha + pass * 1024;
        const uint2* Hb = g_W1Hb + pass * 4096;

        // ---- Stage 1: z1 = x W1 + b1 (both samples); h1, a, s ----
        {
            int j = tid;
            float bv = b1[j];
            float p0 = bv, p1 = 0.f, p2 = 0.f, p3 = 0.f;
            float q0 = bv, q1 = 0.f, q2 = 0.f, q3 = 0.f;
            const float4* x0 = (const float4*)xs;
            const float4* x1 = (const float4*)(xs + 64);
            #pragma unroll 4
            for (int i4 = 0; i4 < 16; i4++) {
                int i = i4 * 4;
                float w0 = W1[(i + 0) * HD + j];
                float w1 = W1[(i + 1) * HD + j];
                float w2 = W1[(i + 2) * HD + j];
                float w3 = W1[(i + 3) * HD + j];
                float4 u0 = x0[i4], u1 = x1[i4];
                p0 = fmaf(u0.x, w0, p0); q0 = fmaf(u1.x, w0, q0);
                p1 = fmaf(u0.y, w1, p1); q1 = fmaf(u1.y, w1, q1);
                p2 = fmaf(u0.z, w2, p2); q2 = fmaf(u1.z, w2, q2);
                p3 = fmaf(u0.w, w3, p3); q3 = fmaf(u1.w, w3, q3);
            }
            float z0v = (p0 + p1) + (p2 + p3);
            float z1v = (q0 + q1) + (q2 + q3);
            #pragma unroll
            for (int ns = 0; ns < 2; ns++) {
                float z = ns ? z1v : z0v;
                float h, a, s;
                if (pass == 0) {
                    float sg = 1.0f / (1.0f + __expf(-z));
                    h = fmaxf(z, 0.0f) + log1pf(__expf(-fabsf(z)));
                    a = sg;
                    s = sg * (1.0f - sg);
                } else {
                    float t = tanhf(0.5f * z);
                    float o = 1.0f - t * t;
                    h = z * t;
                    a = fmaf(0.5f * z, o, t);
                    s = o * (1.0f - 0.5f * z * t);
                }
                vA[ns * 256 + j] = h;
                vC[ns * 256 + j] = a;
                vD[ns * 256 + j] = s;
            }
        }
        __syncthreads();

        // ---- Stage 2: z2 = h1 W2 + b2 ; c, e ----
        {
            int k = tid;
            float bv = b2[k];
            float p0 = bv, p1 = 0.f, p2 = 0.f, p3 = 0.f;
            float q0 = bv, q1 = 0.f, q2 = 0.f, q3 = 0.f;
            const float4* h0 = (const float4*)vA;
            const float4* h1v = (const float4*)(vA + 256);
            #pragma unroll 4
            for (int l4 = 0; l4 < 64; l4++) {
                int l = l4 * 4;
                float w0 = W2[(l + 0) * HD + k];
                float w1 = W2[(l + 1) * HD + k];
                float w2 = W2[(l + 2) * HD + k];
                float w3 = W2[(l + 3) * HD + k];
                float4 u0 = h0[l4], u1 = h1v[l4];
                p0 = fmaf(u0.x, w0, p0); q0 = fmaf(u1.x, w0, q0);
                p1 = fmaf(u0.y, w1, p1); q1 = fmaf(u1.y, w1, q1);
                p2 = fmaf(u0.z, w2, p2); q2 = fmaf(u1.z, w2, q2);
                p3 = fmaf(u0.w, w3, p3); q3 = fmaf(u1.w, w3, q3);
            }
            float z0v = (p0 + p1) + (p2 + p3);
            float z1v = (q0 + q1) + (q2 + q3);
            float w3v = W3[k];
            #pragma unroll
            for (int ns = 0; ns < 2; ns++) {
                float z = ns ? z1v : z0v;
                float a, s;
                if (pass == 0) {
                    float sg = 1.0f / (1.0f + __expf(-z));
                    a = sg;
                    s = sg * (1.0f - sg);
                } else {
                    float t = tanhf(0.5f * z);
                    float o = 1.0f - t * t;
                    a = fmaf(0.5f * z, o, t);
                    s = o * (1.0f - 0.5f * z * t);
                }
                vB[ns * 256 + k] = a * w3v;
                vE[ns * 256 + k] = s * w3v;
            }
        }
        __syncthreads();

        // ---- Stage 3: u = W2 c ; dds = s*u, aus = a*u ----
        {
            int j = tid;
            float p0 = 0.f, p1 = 0.f, p2 = 0.f, p3 = 0.f;
            float q0 = 0.f, q1 = 0.f, q2 = 0.f, q3 = 0.f;
            const float4* c0 = (const float4*)vB;
            const float4* c1 = (const float4*)(vB + 256);
            #pragma unroll 4
            for (int k4 = 0; k4 < 64; k4++) {
                int k = k4 * 4;
                float w0 = W2T[(k + 0) * HD + j];
                float w1 = W2T[(k + 1) * HD + j];
                float w2 = W2T[(k + 2) * HD + j];
                float w3 = W2T[(k + 3) * HD + j];
                float4 u0 = c0[k4], u1 = c1[k4];
                p0 = fmaf(u0.x, w0, p0); q0 = fmaf(u1.x, w0, q0);
                p1 = fmaf(u0.y, w1, p1); q1 = fmaf(u1.y, w1, q1);
                p2 = fmaf(u0.z, w2, p2); q2 = fmaf(u1.z, w2, q2);
                p3 = fmaf(u0.w, w3, p3); q3 = fmaf(u1.w, w3, q3);
            }
            float u0v = (p0 + p1) + (p2 + p3);
            float u1v = (q0 + q1) + (q2 + q3);
            float s0 = vD[j], s1 = vD[256 + j];
            float a0 = vC[j], a1 = vC[256 + j];
            vD[j]       = s0 * u0v;  vD[256 + j] = s1 * u1v;
            vA[j]       = a0 * u0v;  vA[256 + j] = a1 * u1v;
        }
        __syncthreads();

        // ---- Stage 4: g = W1 (a*u), 4-way j-split, both samples ----
        {
            int m = tid & 63, part = tid >> 6;
            const float* W1Tp = W1T + part * 64 * 64;
            const float4* a0 = (const float4*)(vA + part * 64);
            const float4* a1 = (const float4*)(vA + 256 + part * 64);
            float p0 = 0.f, p1 = 0.f, p2 = 0.f, p3 = 0.f;
            float q0 = 0.f, q1 = 0.f, q2 = 0.f, q3 = 0.f;
            #pragma unroll 4
            for (int j4 = 0; j4 < 16; j4++) {
                int jj = j4 * 4;
                float w0 = W1Tp[(jj + 0) * 64 + m];
                float w1 = W1Tp[(jj + 1) * 64 + m];
                float w2 = W1Tp[(jj + 2) * 64 + m];
                float w3 = W1Tp[(jj + 3) * 64 + m];
                float4 u0 = a0[j4], u1 = a1[j4];
                p0 = fmaf(w0, u0.x, p0); q0 = fmaf(w0, u1.x, q0);
                p1 = fmaf(w1, u0.y, p1); q1 = fmaf(w1, u1.y, q1);
                p2 = fmaf(w2, u0.z, p2); q2 = fmaf(w2, u1.z, q2);
                p3 = fmaf(w3, u0.w, p3); q3 = fmaf(w3, u1.w, q3);
            }
            float g0 = (p0 + p1) + (p2 + p3);
            float g1 = (q0 + q1) + (q2 + q3);
            vB[part * 64 + m]       = g0;   // ccs dead after stage 3 sync
            vB[256 + part * 64 + m] = g1;
        }
        __syncthreads();
        // g[0..31] only; Hs2 has 32 rows per sample.
        if (tid < 64) {
            int ns = tid >> 5, mm = tid & 31;
            const float* gp = vB + ns * 256;
            Hs2[ns * 2080 + mm * 65 + 64] += gp[mm] + gp[64 + mm] + gp[128 + mm] + gp[192 + mm];
        }
        __syncthreads();   // vB (gpart) consumed before uEp overwrite

        // ---- pack scale pairs: uCp (aas), uDp (dds), uEp (ees) ----
        {
            int ns = tid >> 7, jp = tid & 127;
            uCp[tid] = pack_bf16x2(vC[ns * 256 + 2 * jp], vC[ns * 256 + 2 * jp + 1]);
            uDp[tid] = pack_bf16x2(vD[ns * 256 + 2 * jp], vD[ns * 256 + 2 * jp + 1]);
            uEp[tid] = pack_bf16x2(vE[ns * 256 + 2 * jp], vE[ns * 256 + 2 * jp + 1]);
        }
        __syncthreads();

        // ---- Stage 5 (bf16 TENSOR, barrier-free): fragments direct from tables ----
        const int mp  = wid & 3;           // m rows mp*32 .. +31 (m' = 2x64)
        const int nh  = wid >> 2;          // n cols nh*64 .. +63
        const int mp2 = mp & 1;
        const int sA  = mp >> 1;           // stage-5 sample
        const int s5  = wid & 1;           // H-phase sample
        const int nH  = (wid >> 1) * 16;   // H-phase col group
        const int nH4 = wid >> 1;

        #pragma unroll 1
        for (int ktile = 0; ktile < 2; ktile++) {
            float acc[2][8][4];
            #pragma unroll
            for (int mi = 0; mi < 2; mi++)
                #pragma unroll
                for (int i = 0; i < 8; i++)
                    #pragma unroll
                    for (int j = 0; j < 4; j++) acc[mi][i][j] = 0.f;

            #pragma unroll 1
            for (int jt4 = 0; jt4 < 16; jt4++) {
                uint32_t w0 = uCp[sA * 128 + jt4 * 8 + t4];
                uint32_t w1 = uCp[sA * 128 + jt4 * 8 + t4 + 4];
                uint4 av0 = Af[((jt4 * 2 + mp2) * 2 + 0) * 32 + lane];
                uint4 av1 = Af[((jt4 * 2 + mp2) * 2 + 1) * 32 + lane];
                uint32_t af0[4] = {hmul2_bf16(av0.x, w0), hmul2_bf16(av0.y, w0),
                                   hmul2_bf16(av0.z, w1), hmul2_bf16(av0.w, w1)};
                uint32_t af1[4] = {hmul2_bf16(av1.x, w0), hmul2_bf16(av1.y, w0),
                                   hmul2_bf16(av1.z, w1), hmul2_bf16(av1.w, w1)};
                const uint2* Bp = Bf + (((ktile * 16 + jt4) * 2 + nh) * 8) * 32 + lane;
                #pragma unroll
                for (int nt = 0; nt < 8; nt++) {
                    uint2 bv = Bp[nt * 32];
                    MMA_BF16(acc[0][nt], af0[0], af0[1], af0[2], af0[3], bv.x, bv.y);
                    MMA_BF16(acc[1][nt], af1[0], af1[1], af1[2], af1[3], bv.x, bv.y);
                }
            }

            // epilogue: MtB[sample][kp][m] = bf16x2(M[n0], M[n0+1])
            {
                uint32_t* Mbase = MtB + sA * 9216;
                #pragma unroll
                for (int mi = 0; mi < 2; mi++) {
                    int mloc = mp2 * 32 + mi * 16 + g;
                    #pragma unroll
                    for (int nt = 0; nt < 8; nt++) {
                        int kp = ktile * 64 + nh * 32 + nt * 4 + t4;
                        Mbase[kp * 72 + mloc]     = pack_bf16x2(acc[mi][nt][0], acc[mi][nt][1]);
                        Mbase[kp * 72 + mloc + 8] = pack_bf16x2(acc[mi][nt][2], acc[mi][nt][3]);
                    }
                }
            }
        }
        __syncthreads();   // all MtB written before H2 reads

        // ---- H2 (bf16, k16): Hs2[s5] += sum_k e_k M[k][32+i] M[k][j] ----
        {
            float hacc[2][2][4];
            #pragma unroll
            for (int a = 0; a < 2; a++)
                #pragma unroll
                for (int c = 0; c < 2; c++)
                    #pragma unroll
                    for (int d = 0; d < 4; d++) hacc[a][c][d] = 0.f;

            const uint32_t* Ms = MtB + s5 * 9216;
            const uint32_t* eP = uEp + s5 * 128;
            #pragma unroll 2
            for (int kpb = 0; kpb < 128; kpb += 8) {
                int kp0 = kpb + t4, kp1 = kpb + t4 + 4;
                uint32_t w0 = eP[kp0], w1 = eP[kp1];
                const uint32_t* r0 = Ms + kp0 * 72;
                const uint32_t* r1 = Ms + kp1 * 72;
                uint32_t af[2][4];
                #pragma unroll
                for (int mi = 0; mi < 2; mi++) {
                    int mH = mi * 16;
                    af[mi][0] = hmul2_bf16(r0[32 + mH + g], w0);
                    af[mi][1] = hmul2_bf16(r0[32 + mH + g + 8], w0);
                    af[mi][2] = hmul2_bf16(r1[32 + mH + g], w1);
                    af[mi][3] = hmul2_bf16(r1[32 + mH + g + 8], w1);
                }
                #pragma unroll
                for (int nt = 0; nt < 2; nt++) {
                    int nb = nH + nt * 8;
                    uint32_t b0 = r0[nb + g];
                    uint32_t b1 = r1[nb + g];
                    MMA_BF16(hacc[0][nt], af[0][0], af[0][1], af[0][2], af[0][3], b0, b1);
                    MMA_BF16(hacc[1][nt], af[1][0], af[1][1], af[1][2], af[1][3], b0, b1);
                }
            }

            // ---- H1 (bf16, k16, fragments from tables, barrier-free) ----
            const uint32_t* dP = uDp + s5 * 128;
            #pragma unroll 2
            for (int kpb4 = 0; kpb4 < 16; kpb4++) {
                uint32_t w0 = dP[kpb4 * 8 + t4], w1 = dP[kpb4 * 8 + t4 + 4];
                uint4 av0 = Ha[(kpb4 * 2 + 0) * 32 + lane];
                uint4 av1 = Ha[(kpb4 * 2 + 1) * 32 + lane];
                uint32_t af0[4] = {hmul2_bf16(av0.x, w0), hmul2_bf16(av0.y, w0),
                                   hmul2_bf16(av0.z, w1), hmul2_bf16(av0.w, w1)};
                uint32_t af1[4] = {hmul2_bf16(av1.x, w0), hmul2_bf16(av1.y, w0),
                                   hmul2_bf16(av1.z, w1), hmul2_bf16(av1.w, w1)};
                #pragma unroll
                for (int nt = 0; nt < 2; nt++) {
                    uint2 bv = Hb[((kpb4 * 4 + nH4) * 2 + nt) * 32 + lane];
                    MMA_BF16(hacc[0][nt], af0[0], af0[1], af0[2], af0[3], bv.x, bv.y);
                    MMA_BF16(hacc[1][nt], af1[0], af1[1], af1[2], af1[3], bv.x, bv.y);
                }
            }

            float* HsS = Hs2 + s5 * 2080;
            #pragma unroll
            for (int mi = 0; mi < 2; mi++)
                #pragma unroll
                for (int nt = 0; nt < 2; nt++) {
                    int j0 = nH + nt * 8 + t4 * 2;
                    int row = mi * 16 + g;
                    HsS[row * 65 + j0]           += hacc[mi][nt][0];
                    HsS[row * 65 + j0 + 1]       += hacc[mi][nt][1];
                    HsS[(row + 8) * 65 + j0]     += hacc[mi][nt][2];
                    HsS[(row + 8) * 65 + j0 + 1] += hacc[mi][nt][3];
                }
        }
        __syncthreads();
    }

    // ---- Solve (2 warps, one per sample) ----
    float* Sv = MtBf;   // dead
    if (tid < 64) {
        int ws = tid >> 5, ln = tid & 31;
        const float* HsS = Hs2 + ws * 2080;
        float* SvN = Sv + ws * 1088;
        const float* qd = xs + ws * 64 + 32;
        float r = HsS[ln * 65 + 64];   // gsA
        #pragma unroll 8
        for (int j = 0; j < 32; j++) r -= HsS[ln * 65 + j] * qd[j];
        #pragma unroll 8
        for (int j = 0; j < 32; j++)
            SvN[ln * 34 + j] = HsS[ln * 65 + 32 + j] + ((ln == j) ? 2.0f : 0.0f);
        SvN[ln * 34 + 32] = r;
        __syncwarp();

        for (int p = 0; p < 32; p++) {
            float v = (ln >= p) ? fabsf(SvN[ln * 34 + p]) : -1.0f;
            int idx = ln;
            #pragma unroll
            for (int off = 16; off; off >>= 1) {
                float v2 = __shfl_xor_sync(0xffffffffu, v, off);
                int   i2 = __shfl_xor_sync(0xffffffffu, idx, off);
                if (v2 > v || (v2 == v && i2 < idx)) { v = v2; idx = i2; }
            }
            if (idx != p) {
                float t1 = SvN[p * 34 + ln];
                SvN[p * 34 + ln]   = SvN[idx * 34 + ln];
                SvN[idx * 34 + ln] = t1;
                if (ln == 0) {
                    float t2 = SvN[p * 34 + 32];
                    SvN[p * 34 + 32]   = SvN[idx * 34 + 32];
                    SvN[idx * 34 + 32] = t2;
                }
            }
            __syncwarp();
            float pinvv = 1.0f / SvN[p * 34 + p];
            if (ln != p) {
                float f = SvN[ln * 34 + p] * pinvv;
                for (int c = p; c < 33; c++)
                    SvN[ln * 34 + c] -= f * SvN[p * 34 + c];
            }
            __syncwarp();
        }
        float qdd = SvN[ln * 34 + 32] / SvN[ln * 34 + ln];
        int sample = b * 2 + ws;
        out[sample * 64 + ln]      = xs[ws * 64 + 32 + ln];
        out[sample * 64 + 32 + ln] = qdd;
    }
}

extern "C" void kernel_launch(void* const* d_in, const int* in_sizes, int n_in,
                              void* d_out, int out_size)
{
    const float* x   = (const float*)d_in[0];
    const float* W1m = (const float*)d_in[1];
    const float* b1m = (const float*)d_in[2];
    const float* W2m = (const float*)d_in[3];
    const float* b2m = (const float*)d_in[4];
    const float* W3m = (const float*)d_in[5];
    const float* W1q = (const float*)d_in[6];
    const float* b1q = (const float*)d_in[7];
    const float* W2q = (const float*)d_in[8];
    const float* b2q = (const float*)d_in[9];
    const float* W3q = (const float*)d_in[10];
    float* out = (float*)d_out;

    int B = in_sizes[0] / 64;

    prep_kernel<<<256, 256>>>(W1m, W2m, W1q, W2q);
    cudaFuncSetAttribute(lnn_kernel, cudaFuncAttributeMaxDynamicSharedMemorySize, SMEM_BYTES);
    lnn_kernel<<<B / 2, 256, SMEM_BYTES>>>(x, W1m, b1m, W2m, b2m, W3m,
                                           W1q, b1q, W2q, b2q, W3q, out);
}